// round 1
// baseline (speedup 1.0000x reference)
#include <cuda_runtime.h>
#include <math.h>

#define TOK 32768   // L = 32^3 tokens
#define CH  512

// ---------------- scratch (no cudaMalloc allowed) ----------------
__device__ float g_img[(size_t)CH * TOK];     // (C, L)  K-major LN1 output
__device__ float g_qkv[(size_t)TOK * 1536];   // (L, 3C) row-major
__device__ float g_att[(size_t)TOK * CH];     // (L, C)  lepe + attention out
__device__ float g_xf [(size_t)TOK * CH];     // (L, C)  after proj + residual
__device__ float g_ln2[(size_t)TOK * CH];     // (L, C)  LN2 output
__device__ float g_mid[(size_t)TOK * 2048];   // (L, 2048) gelu(fc1)

// ---------------- LN1: channel-first input -> (C,L) normalized ----------------
__global__ void ln1_kernel(const float* __restrict__ x,
                           const float* __restrict__ gam,
                           const float* __restrict__ bet,
                           float* __restrict__ img)
{
    int tok = blockIdx.x * blockDim.x + threadIdx.x;
    float sum = 0.f, sq = 0.f;
    for (int c = 0; c < CH; c++) {
        float v = x[(size_t)c * TOK + tok];
        sum += v; sq += v * v;
    }
    float mean = sum * (1.f / CH);
    float var  = sq * (1.f / CH) - mean * mean;
    float rstd = rsqrtf(var + 1e-5f);
    for (int c = 0; c < CH; c++) {
        float v = x[(size_t)c * TOK + tok];
        img[(size_t)c * TOK + tok] = (v - mean) * rstd * gam[c] + bet[c];
    }
}

// ---------------- SGEMM: C[MxN] = A[MxK] * B[KxN] (+ epilogue) ----------------
// AROW=0: A stored K-major, A[k*M+m].  AROW=1: A row-major, A[m*K+k].
// EPI: 0 none | 1 +bias | 2 gelu(x+bias) | 3 +bias + resC[n*M+m], row-major out
//      4 +bias + resR[m*N+n], write col-major out[n*M+m]
template<int AROW, int EPI>
__global__ __launch_bounds__(256, 2)
void sgemm_kernel(const float* __restrict__ A, const float* __restrict__ B,
                  float* __restrict__ Cout, const float* __restrict__ bias,
                  const float* __restrict__ resR, const float* __restrict__ resC,
                  int M, int N, int K)
{
    __shared__ float As[16][132];
    __shared__ float Bs[16][128];
    const int tid = threadIdx.x;
    const int m0 = blockIdx.y * 128;
    const int n0 = blockIdx.x * 128;
    const int tm = tid >> 4;      // 0..15
    const int tn = tid & 15;      // 0..15

    float acc[8][8];
#pragma unroll
    for (int i = 0; i < 8; i++)
#pragma unroll
        for (int j = 0; j < 8; j++) acc[i][j] = 0.f;

    for (int k0 = 0; k0 < K; k0 += 16) {
#pragma unroll
        for (int r = 0; r < 2; r++) {
            int f = tid + r * 256;          // 0..511
            if (AROW) {
                int i  = f >> 2;
                int j4 = (f & 3) * 4;
                float4 v = *(const float4*)&A[(size_t)(m0 + i) * K + k0 + j4];
                As[j4 + 0][i] = v.x; As[j4 + 1][i] = v.y;
                As[j4 + 2][i] = v.z; As[j4 + 3][i] = v.w;
            } else {
                int j  = f >> 5;
                int i4 = (f & 31) * 4;
                float4 v = *(const float4*)&A[(size_t)(k0 + j) * M + m0 + i4];
                *(float4*)&As[j][i4] = v;
            }
            int jb = f >> 5;
            int n4 = (f & 31) * 4;
            float4 vb = *(const float4*)&B[(size_t)(k0 + jb) * N + n0 + n4];
            *(float4*)&Bs[jb][n4] = vb;
        }
        __syncthreads();
#pragma unroll
        for (int k = 0; k < 16; k++) {
            float a[8], b[8];
            *(float4*)&a[0] = *(const float4*)&As[k][tm * 4];
            *(float4*)&a[4] = *(const float4*)&As[k][64 + tm * 4];
            *(float4*)&b[0] = *(const float4*)&Bs[k][tn * 4];
            *(float4*)&b[4] = *(const float4*)&Bs[k][64 + tn * 4];
#pragma unroll
            for (int i = 0; i < 8; i++)
#pragma unroll
                for (int j = 0; j < 8; j++)
                    acc[i][j] += a[i] * b[j];
        }
        __syncthreads();
    }

    // epilogue
#pragma unroll
    for (int vm = 0; vm < 2; vm++)
#pragma unroll
    for (int u = 0; u < 4; u++) {
        int m = m0 + vm * 64 + tm * 4 + u;
#pragma unroll
        for (int vn = 0; vn < 2; vn++) {
            int n = n0 + vn * 64 + tn * 4;
            float tv[4];
#pragma unroll
            for (int w = 0; w < 4; w++) tv[w] = acc[vm * 4 + u][vn * 4 + w];
            if (EPI >= 1) {
#pragma unroll
                for (int w = 0; w < 4; w++) tv[w] += bias[n + w];
            }
            if (EPI == 2) {
#pragma unroll
                for (int w = 0; w < 4; w++) {
                    float z = tv[w];
                    tv[w] = 0.5f * z * (1.f + erff(z * 0.70710678118654752f));
                }
            }
            if (EPI == 3) {
#pragma unroll
                for (int w = 0; w < 4; w++)
                    tv[w] += resC[(size_t)(n + w) * M + m];
            }
            if (EPI == 4) {
#pragma unroll
                for (int w = 0; w < 4; w++) {
                    float z = tv[w] + resR[(size_t)m * N + n + w];
                    Cout[(size_t)(n + w) * M + m] = z;   // transposed final write
                }
            } else {
                float4 o;
                o.x = tv[0]; o.y = tv[1]; o.z = tv[2]; o.w = tv[3];
                *(float4*)&Cout[(size_t)m * N + n] = o;
            }
        }
    }
}

// ---------------- LePE: depthwise 3x3 within each window -> att ----------------
__global__ __launch_bounds__(256)
void lepe_kernel(const float* __restrict__ qkv,
                 const float* __restrict__ w0, const float* __restrict__ b0,
                 const float* __restrict__ w1, const float* __restrict__ b1,
                 float* __restrict__ att)
{
    int bw = blockIdx.x;            // 0..511
    int branch = bw >> 8;
    int widx = bw & 255;
    int d = widx >> 3, g = widx & 7;
    int c = threadIdx.x;            // 0..255 (channel within branch)

    const float* W  = branch ? w1 : w0;
    const float* Bv = branch ? b1 : b0;
    float w[9];
#pragma unroll
    for (int r = 0; r < 9; r++) w[r] = W[c * 9 + r];
    float bias = Bv[c];

    const int Hs = branch ? 4 : 32;
    const int Ws = branch ? 32 : 4;
    const int shift = branch ? 5 : 2;
    const int mask  = Ws - 1;
    const size_t voff = 1024 + branch * 256 + c;

    for (int t = 0; t < 128; t++) {
        int i = t >> shift;
        int j = t & mask;
        float acc = bias;
#pragma unroll
        for (int di = -1; di <= 1; di++) {
            int ii = i + di;
            if (ii < 0 || ii >= Hs) continue;
#pragma unroll
            for (int dj = -1; dj <= 1; dj++) {
                int jj = j + dj;
                if (jj < 0 || jj >= Ws) continue;
                int ll = (branch == 0) ? d * 1024 + ii * 32 + g * 4 + jj
                                       : d * 1024 + (g * 4 + ii) * 32 + jj;
                acc += w[(di + 1) * 3 + (dj + 1)] * qkv[(size_t)ll * 1536 + voff];
            }
        }
        int l = (branch == 0) ? d * 1024 + i * 32 + g * 4 + j
                              : d * 1024 + g * 128 + t;
        att[(size_t)l * 512 + branch * 256 + c] = acc;
    }
}

// ---------------- windowed attention: one block per (branch, window, head) ----
__global__ __launch_bounds__(128)
void attn_kernel(const float* __restrict__ qkv, float* __restrict__ att)
{
    __shared__ float ks[128][36];
    __shared__ float vs[128][36];
    const int t = threadIdx.x;
    const int bid = blockIdx.x;          // 0..4095
    const int head   = bid & 7;
    const int widx   = (bid >> 3) & 255;
    const int branch = bid >> 11;
    const int d = widx >> 3, g = widx & 7;

    int l;
    if (branch == 0) l = d * 1024 + (t >> 2) * 32 + g * 4 + (t & 3);
    else             l = d * 1024 + g * 128 + t;
    const int cc = branch * 256 + head * 32;
    const size_t base = (size_t)l * 1536 + cc;

    float q[32];
#pragma unroll
    for (int u = 0; u < 8; u++) {
        float4 vq = *(const float4*)&qkv[base + u * 4];
        q[u*4+0] = vq.x; q[u*4+1] = vq.y; q[u*4+2] = vq.z; q[u*4+3] = vq.w;
        *(float4*)&ks[t][u * 4] = *(const float4*)&qkv[base + 512  + u * 4];
        *(float4*)&vs[t][u * 4] = *(const float4*)&qkv[base + 1024 + u * 4];
    }
    __syncthreads();

    const float scale = 0.17677669529663687f;  // 32^-0.5
    float m = -1e30f, lsum = 0.f;
    for (int j = 0; j < 128; j++) {
        float s = 0.f;
#pragma unroll
        for (int u = 0; u < 32; u++) s += q[u] * ks[j][u];
        s *= scale;
        float nm = fmaxf(m, s);
        lsum = lsum * __expf(m - nm) + __expf(s - nm);
        m = nm;
    }
    float o[32];
#pragma unroll
    for (int u = 0; u < 32; u++) o[u] = 0.f;
    for (int j = 0; j < 128; j++) {
        float s = 0.f;
#pragma unroll
        for (int u = 0; u < 32; u++) s += q[u] * ks[j][u];
        float p = __expf(s * scale - m);
#pragma unroll
        for (int u = 0; u < 32; u++) o[u] += p * vs[j][u];
    }
    float inv = 1.f / lsum;
    const size_t ob = (size_t)l * 512 + cc;
#pragma unroll
    for (int u = 0; u < 32; u++)
        att[ob + u] = att[ob + u] + o[u] * inv;   // att preloaded with lepe
}

// ---------------- LN2: warp per token, row-major in/out ----------------
__global__ void ln2_kernel(const float* __restrict__ xf,
                           const float* __restrict__ gam,
                           const float* __restrict__ bet,
                           float* __restrict__ out)
{
    int warp = (blockIdx.x * blockDim.x + threadIdx.x) >> 5;
    int lane = threadIdx.x & 31;
    size_t base = (size_t)warp * 512;
    float vals[16];
    float sum = 0.f, sq = 0.f;
#pragma unroll
    for (int u = 0; u < 16; u++) {
        float v = xf[base + lane + u * 32];
        vals[u] = v; sum += v; sq += v * v;
    }
#pragma unroll
    for (int o = 16; o > 0; o >>= 1) {
        sum += __shfl_xor_sync(0xffffffffu, sum, o);
        sq  += __shfl_xor_sync(0xffffffffu, sq, o);
    }
    float mean = sum * (1.f / 512.f);
    float var  = sq  * (1.f / 512.f) - mean * mean;
    float rstd = rsqrtf(var + 1e-5f);
#pragma unroll
    for (int u = 0; u < 16; u++) {
        int c = lane + u * 32;
        out[base + c] = (vals[u] - mean) * rstd * gam[c] + bet[c];
    }
}

// ---------------- launch ----------------
extern "C" void kernel_launch(void* const* d_in, const int* in_sizes, int n_in,
                              void* d_out, int out_size)
{
    const float* x    = (const float*)d_in[0];
    const float* n1g  = (const float*)d_in[1];
    const float* n1b  = (const float*)d_in[2];
    const float* qkvw = (const float*)d_in[3];
    const float* l0w  = (const float*)d_in[4];
    const float* l0b  = (const float*)d_in[5];
    const float* l1w  = (const float*)d_in[6];
    const float* l1b  = (const float*)d_in[7];
    const float* pw   = (const float*)d_in[8];
    const float* pb   = (const float*)d_in[9];
    const float* n2g  = (const float*)d_in[10];
    const float* n2b  = (const float*)d_in[11];
    const float* f1w  = (const float*)d_in[12];
    const float* f1b  = (const float*)d_in[13];
    const float* f2w  = (const float*)d_in[14];
    const float* f2b  = (const float*)d_in[15];
    float* out = (float*)d_out;

    float *img, *qkv, *att, *xf, *ln2o, *mid;
    cudaGetSymbolAddress((void**)&img,  g_img);
    cudaGetSymbolAddress((void**)&qkv,  g_qkv);
    cudaGetSymbolAddress((void**)&att,  g_att);
    cudaGetSymbolAddress((void**)&xf,   g_xf);
    cudaGetSymbolAddress((void**)&ln2o, g_ln2);
    cudaGetSymbolAddress((void**)&mid,  g_mid);

    // 1. LN1
    ln1_kernel<<<TOK / 128, 128>>>(x, n1g, n1b, img);
    // 2. QKV GEMM (A K-major)
    sgemm_kernel<0, 0><<<dim3(1536 / 128, TOK / 128), 256>>>(
        img, qkvw, qkv, nullptr, nullptr, nullptr, TOK, 1536, 512);
    // 3. LePE into att, then attention accumulates on top
    lepe_kernel<<<512, 256>>>(qkv, l0w, l0b, l1w, l1b, att);
    attn_kernel<<<4096, 128>>>(qkv, att);
    // 4. proj + bias + x residual (col-major residual) -> xf
    sgemm_kernel<1, 3><<<dim3(512 / 128, TOK / 128), 256>>>(
        att, pw, xf, pb, nullptr, x, TOK, 512, 512);
    // 5. LN2
    ln2_kernel<<<TOK / 8, 256>>>(xf, n2g, n2b, ln2o);
    // 6. fc1 + bias + exact GELU
    sgemm_kernel<1, 2><<<dim3(2048 / 128, TOK / 128), 256>>>(
        ln2o, f1w, mid, f1b, nullptr, nullptr, TOK, 2048, 512);
    // 7. fc2 + bias + xf residual, transposed write to channel-first output
    sgemm_kernel<1, 4><<<dim3(512 / 128, TOK / 128), 256>>>(
        mid, f2w, out, f2b, xf, nullptr, TOK, 512, 2048);
}

// round 4
// speedup vs baseline: 3.3973x; 3.3973x over previous
#include <cuda_runtime.h>
#include <cuda_fp16.h>
#include <math.h>
#include <stdint.h>

#define TOK 32768

// ======================= scratch (no cudaMalloc allowed) =======================
__device__ __half g_img[(size_t)TOK * 512];     // LN1 out, (L,C) row-major fp16
__device__ __half g_wq [(size_t)1536 * 512];    // qkv_w^T  (N,K) fp16
__device__ __half g_wp [(size_t)512 * 512];     // proj_w^T
__device__ __half g_w1 [(size_t)2048 * 512];    // fc1_w^T
__device__ __half g_w2 [(size_t)512 * 2048];    // fc2_w^T
__device__ float  g_qkv[(size_t)TOK * 1536];    // (L,3C) fp32 row-major
__device__ __half g_att[(size_t)TOK * 512];     // lepe+attn out, (L,C) fp16
__device__ float  g_xf [(size_t)512 * TOK];     // (C,L) fp32 col-major
__device__ __half g_h2 [(size_t)TOK * 512];     // LN2 out fp16 (L,C)
__device__ __half g_mid[(size_t)TOK * 2048];    // gelu(fc1) fp16 (L,2048)

// ======================= PTX helpers (sm_80-level only) =======================
__device__ __forceinline__ uint32_t smem_u32(const void* p) {
    uint32_t a;
    asm("{ .reg .u64 t; cvta.to.shared.u64 t, %1; cvt.u32.u64 %0, t; }" : "=r"(a) : "l"(p));
    return a;
}
__device__ __forceinline__ void ldm4(uint32_t* r, uint32_t a) {
    asm volatile("ldmatrix.sync.aligned.m8n8.x4.shared.b16 {%0,%1,%2,%3}, [%4];"
        : "=r"(r[0]), "=r"(r[1]), "=r"(r[2]), "=r"(r[3]) : "r"(a));
}
__device__ __forceinline__ void mma16816(float* d, const uint32_t* a, const uint32_t* b) {
    asm volatile("mma.sync.aligned.m16n8k16.row.col.f32.f16.f16.f32 "
        "{%0,%1,%2,%3}, {%4,%5,%6,%7}, {%8,%9}, {%0,%1,%2,%3};"
        : "+f"(d[0]), "+f"(d[1]), "+f"(d[2]), "+f"(d[3])
        : "r"(a[0]), "r"(a[1]), "r"(a[2]), "r"(a[3]), "r"(b[0]), "r"(b[1]));
}

// ======================= HMMA GEMM =======================
// C[M,N] = A[M,K](fp16 row-major) * Bw[N,K]^T (fp16, K contiguous per row)
// EPI 0: fp32 row-major out (ld=ldo)
// EPI 1: fp32 col-major out[n*M+m] = acc + bias[n] + res[n*M+m]
// EPI 2: fp16 row-major out = gelu(acc + bias[n]), ld=ldo
#define TSTR 40   // smem row stride in halves (80 B)
template<int EPI>
__global__ __launch_bounds__(256)
void gemm_hmma(const __half* __restrict__ A, const __half* __restrict__ Bw,
               const float* __restrict__ bias, const float* __restrict__ res,
               void* __restrict__ outp, int M, int ldo, int K)
{
    __shared__ __half sA[2][128 * TSTR];
    __shared__ __half sB[2][128 * TSTR];
    const int tid  = threadIdx.x;
    const int lane = tid & 31;
    const int warp = tid >> 5;
    const int wm = warp & 1;        // 2 warps along M
    const int wn = warp >> 1;       // 4 warps along N
    const int m0 = blockIdx.y * 128;
    const int n0 = blockIdx.x * 128;

    float acc[4][4][4];
#pragma unroll
    for (int i = 0; i < 4; i++)
#pragma unroll
        for (int j = 0; j < 4; j++)
#pragma unroll
            for (int k = 0; k < 4; k++) acc[i][j][k] = 0.f;

    const int chunks = K >> 5;           // K-chunk = 32
    const int grow = tid >> 2;           // 0..63  (with i*64 offset -> 0..127)
    const int gcol = (tid & 3) * 8;      // halves

    uint4 ra[2], rb[2];
#pragma unroll
    for (int i = 0; i < 2; i++) {
        int r = grow + i * 64;
        ra[i] = *(const uint4*)&A [(size_t)(m0 + r) * K + gcol];
        rb[i] = *(const uint4*)&Bw[(size_t)(n0 + r) * K + gcol];
    }
#pragma unroll
    for (int i = 0; i < 2; i++) {
        int r = grow + i * 64;
        *(uint4*)&sA[0][r * TSTR + gcol] = ra[i];
        *(uint4*)&sB[0][r * TSTR + gcol] = rb[i];
    }
    __syncthreads();

    for (int c = 0; c < chunks; c++) {
        const int buf = c & 1;
        if (c + 1 < chunks) {
            int koff = (c + 1) * 32;
#pragma unroll
            for (int i = 0; i < 2; i++) {
                int r = grow + i * 64;
                ra[i] = *(const uint4*)&A [(size_t)(m0 + r) * K + koff + gcol];
                rb[i] = *(const uint4*)&Bw[(size_t)(n0 + r) * K + koff + gcol];
            }
        }
        const uint32_t baseA = smem_u32(sA[buf]);
        const uint32_t baseB = smem_u32(sB[buf]);
#pragma unroll
        for (int kk = 0; kk < 2; kk++) {
            uint32_t af[4][4];
#pragma unroll
            for (int mt = 0; mt < 4; mt++) {
                int row = wm * 64 + mt * 16 + (lane & 15);
                int col = kk * 16 + ((lane >> 4) << 3);
                ldm4(af[mt], baseA + (uint32_t)(row * TSTR + col) * 2);
            }
            uint32_t bf[4][2];
#pragma unroll
            for (int pr = 0; pr < 2; pr++) {
                int row = wn * 32 + pr * 16 + ((lane >> 4) & 1) * 8 + (lane & 7);
                int col = kk * 16 + ((lane >> 3) & 1) * 8;
                uint32_t t4[4];
                ldm4(t4, baseB + (uint32_t)(row * TSTR + col) * 2);
                bf[pr * 2][0] = t4[0]; bf[pr * 2][1] = t4[1];
                bf[pr * 2 + 1][0] = t4[2]; bf[pr * 2 + 1][1] = t4[3];
            }
#pragma unroll
            for (int mt = 0; mt < 4; mt++)
#pragma unroll
                for (int nt = 0; nt < 4; nt++)
                    mma16816(acc[mt][nt], af[mt], bf[nt]);
        }
        __syncthreads();
        if (c + 1 < chunks) {
            const int nb = (c + 1) & 1;
#pragma unroll
            for (int i = 0; i < 2; i++) {
                int r = grow + i * 64;
                *(uint4*)&sA[nb][r * TSTR + gcol] = ra[i];
                *(uint4*)&sB[nb][r * TSTR + gcol] = rb[i];
            }
            __syncthreads();
        }
    }

    // ---------------- epilogue ----------------
#pragma unroll
    for (int mt = 0; mt < 4; mt++) {
        int r = m0 + wm * 64 + mt * 16 + (lane >> 2);
#pragma unroll
        for (int nt = 0; nt < 4; nt++) {
            int cN = n0 + wn * 32 + nt * 8 + 2 * (lane & 3);
            float v0 = acc[mt][nt][0], v1 = acc[mt][nt][1];
            float v2 = acc[mt][nt][2], v3 = acc[mt][nt][3];
            if (EPI >= 1) {
                float b0 = __ldg(&bias[cN]), b1 = __ldg(&bias[cN + 1]);
                v0 += b0; v1 += b1; v2 += b0; v3 += b1;
            }
            if (EPI == 2) {
                v0 = 0.5f * v0 * (1.f + erff(v0 * 0.70710678118654752f));
                v1 = 0.5f * v1 * (1.f + erff(v1 * 0.70710678118654752f));
                v2 = 0.5f * v2 * (1.f + erff(v2 * 0.70710678118654752f));
                v3 = 0.5f * v3 * (1.f + erff(v3 * 0.70710678118654752f));
            }
            if (EPI == 1) {
                float* o = (float*)outp;
                size_t i00 = (size_t)cN * M + r;
                size_t i01 = (size_t)(cN + 1) * M + r;
                v0 += __ldg(&res[i00]);     v1 += __ldg(&res[i01]);
                v2 += __ldg(&res[i00 + 8]); v3 += __ldg(&res[i01 + 8]);
                o[i00] = v0; o[i01] = v1; o[i00 + 8] = v2; o[i01 + 8] = v3;
            } else if (EPI == 0) {
                float* o = (float*)outp;
                *(float2*)&o[(size_t)r * ldo + cN]       = make_float2(v0, v1);
                *(float2*)&o[(size_t)(r + 8) * ldo + cN] = make_float2(v2, v3);
            } else {
                __half* o = (__half*)outp;
                *(__half2*)&o[(size_t)r * ldo + cN]       = __floats2half2_rn(v0, v1);
                *(__half2*)&o[(size_t)(r + 8) * ldo + cN] = __floats2half2_rn(v2, v3);
            }
        }
    }
}

// ======================= weight transpose + fp16 convert =======================
__global__ void wtrans(const float* __restrict__ w, __half* __restrict__ wT, int K, int N)
{
    __shared__ float s[32][33];
    int n0 = blockIdx.x * 32, k0 = blockIdx.y * 32;
    int tx = threadIdx.x, ty = threadIdx.y;
    for (int i = ty; i < 32; i += 8) s[i][tx] = w[(size_t)(k0 + i) * N + n0 + tx];
    __syncthreads();
    for (int i = ty; i < 32; i += 8) wT[(size_t)(n0 + i) * K + k0 + tx] = __float2half(s[tx][i]);
}

// ======================= LN: (C,L) fp32 -> (L,C) fp16 (static smem) =======================
__global__ __launch_bounds__(256)
void ln_kernel(const float* __restrict__ in, const float* __restrict__ g,
               const float* __restrict__ b, __half* __restrict__ out)
{
    __shared__ __half stg[32 * 520];
    __shared__ float red[512];
    __shared__ float ms[32], rs[32];
    int tx = threadIdx.x & 31, ty = threadIdx.x >> 5;
    int tok = blockIdx.x * 32 + tx;
    float sum = 0.f, sq = 0.f;
    for (int c = ty; c < 512; c += 8) {
        float x = in[(size_t)c * TOK + tok];
        sum += x; sq += x * x;
    }
    red[ty * 32 + tx] = sum; red[256 + ty * 32 + tx] = sq;
    __syncthreads();
    if (ty == 0) {
        float s = 0.f, q = 0.f;
        for (int j = 0; j < 8; j++) { s += red[j * 32 + tx]; q += red[256 + j * 32 + tx]; }
        float mean = s * (1.f / 512.f);
        float var  = q * (1.f / 512.f) - mean * mean;
        ms[tx] = mean; rs[tx] = rsqrtf(var + 1e-5f);
    }
    __syncthreads();
    for (int c = ty; c < 512; c += 8) {
        float x = in[(size_t)c * TOK + tok];
        stg[tx * 520 + c] = __float2half((x - ms[tx]) * rs[tx] * g[c] + b[c]);
    }
    __syncthreads();
    size_t base = (size_t)blockIdx.x * 32 * 512;
#pragma unroll
    for (int i = 0; i < 8; i++) {
        int id = threadIdx.x + i * 256;
        int row = id >> 6, c8 = (id & 63) * 8;
        *(uint4*)&out[base + (size_t)row * 512 + c8] = *(uint4*)&stg[row * 520 + c8];
    }
}

// ======================= LePE (depthwise 3x3 per window) =======================
__global__ __launch_bounds__(256)
void lepe_kernel(const float* __restrict__ qkv,
                 const float* __restrict__ w0, const float* __restrict__ b0,
                 const float* __restrict__ w1, const float* __restrict__ b1,
                 __half* __restrict__ att)
{
    int bw = blockIdx.x;
    int branch = bw >> 8;
    int widx = bw & 255;
    int d = widx >> 3, g = widx & 7;
    int c = threadIdx.x;

    const float* W  = branch ? w1 : w0;
    const float* Bv = branch ? b1 : b0;
    float w[9];
#pragma unroll
    for (int r = 0; r < 9; r++) w[r] = W[c * 9 + r];
    float bias = Bv[c];

    const int Hs = branch ? 4 : 32;
    const int Ws = branch ? 32 : 4;
    const int shift = branch ? 5 : 2;
    const int mask = Ws - 1;
    const size_t voff = 1024 + branch * 256 + c;

    for (int t = 0; t < 128; t++) {
        int i = t >> shift, j = t & mask;
        float acc = bias;
#pragma unroll
        for (int di = -1; di <= 1; di++) {
            int ii = i + di;
            if (ii < 0 || ii >= Hs) continue;
#pragma unroll
            for (int dj = -1; dj <= 1; dj++) {
                int jj = j + dj;
                if (jj < 0 || jj >= Ws) continue;
                int ll = (branch == 0) ? d * 1024 + ii * 32 + g * 4 + jj
                                       : d * 1024 + (g * 4 + ii) * 32 + jj;
                acc += w[(di + 1) * 3 + (dj + 1)] * qkv[(size_t)ll * 1536 + voff];
            }
        }
        int l = (branch == 0) ? d * 1024 + i * 32 + g * 4 + j
                              : d * 1024 + g * 128 + t;
        att[(size_t)l * 512 + branch * 256 + c] = __float2half(acc);
    }
}

// ======================= windowed attention (single pass) =======================
__global__ __launch_bounds__(128)
void attn_kernel(const float* __restrict__ qkv, __half* __restrict__ att)
{
    __shared__ float ks[128][36];
    __shared__ float vs[128][36];
    const int t = threadIdx.x;
    const int bid = blockIdx.x;
    const int head = bid & 7;
    const int widx = (bid >> 3) & 255;
    const int branch = bid >> 11;
    const int d = widx >> 3, g = widx & 7;

    int l;
    if (branch == 0) l = d * 1024 + (t >> 2) * 32 + g * 4 + (t & 3);
    else             l = d * 1024 + g * 128 + t;
    const int cc = branch * 256 + head * 32;
    const size_t base = (size_t)l * 1536 + cc;

    float q[32];
#pragma unroll
    for (int u = 0; u < 8; u++) {
        float4 vq = *(const float4*)&qkv[base + u * 4];
        q[u * 4 + 0] = vq.x; q[u * 4 + 1] = vq.y; q[u * 4 + 2] = vq.z; q[u * 4 + 3] = vq.w;
        *(float4*)&ks[t][u * 4] = *(const float4*)&qkv[base + 512 + u * 4];
        *(float4*)&vs[t][u * 4] = *(const float4*)&qkv[base + 1024 + u * 4];
    }
    __syncthreads();

    const float scale = 0.17677669529663687f;
    float lsum = 0.f;
    float o[32];
#pragma unroll
    for (int u = 0; u < 32; u++) o[u] = 0.f;
    for (int j = 0; j < 128; j++) {
        float s = 0.f;
#pragma unroll
        for (int u = 0; u < 32; u++) s += q[u] * ks[j][u];
        float p = __expf(s * scale);
        lsum += p;
#pragma unroll
        for (int u = 0; u < 32; u++) o[u] += p * vs[j][u];
    }
    float inv = 1.f / lsum;
    __half* ap = att + (size_t)l * 512 + cc;
#pragma unroll
    for (int u = 0; u < 16; u++) {
        __half2 prev = *(__half2*)(ap + 2 * u);
        float2 pf = __half22float2(prev);
        *(__half2*)(ap + 2 * u) =
            __floats2half2_rn(pf.x + o[2 * u] * inv, pf.y + o[2 * u + 1] * inv);
    }
}

// ======================= launch =======================
extern "C" void kernel_launch(void* const* d_in, const int* in_sizes, int n_in,
                              void* d_out, int out_size)
{
    const float* x    = (const float*)d_in[0];
    const float* n1g  = (const float*)d_in[1];
    const float* n1b  = (const float*)d_in[2];
    const float* qkvw = (const float*)d_in[3];
    const float* l0w  = (const float*)d_in[4];
    const float* l0b  = (const float*)d_in[5];
    const float* l1w  = (const float*)d_in[6];
    const float* l1b  = (const float*)d_in[7];
    const float* pw   = (const float*)d_in[8];
    const float* pb   = (const float*)d_in[9];
    const float* n2g  = (const float*)d_in[10];
    const float* n2b  = (const float*)d_in[11];
    const float* f1w  = (const float*)d_in[12];
    const float* f1b  = (const float*)d_in[13];
    const float* f2w  = (const float*)d_in[14];
    const float* f2b  = (const float*)d_in[15];
    float* out = (float*)d_out;

    __half *img, *wq, *wp, *w1, *w2, *att, *h2, *mid;
    float *qkv, *xf;
    cudaGetSymbolAddress((void**)&img, g_img);
    cudaGetSymbolAddress((void**)&wq,  g_wq);
    cudaGetSymbolAddress((void**)&wp,  g_wp);
    cudaGetSymbolAddress((void**)&w1,  g_w1);
    cudaGetSymbolAddress((void**)&w2,  g_w2);
    cudaGetSymbolAddress((void**)&qkv, g_qkv);
    cudaGetSymbolAddress((void**)&att, g_att);
    cudaGetSymbolAddress((void**)&xf,  g_xf);
    cudaGetSymbolAddress((void**)&h2,  g_h2);
    cudaGetSymbolAddress((void**)&mid, g_mid);

    // weight transposes (fp32 -> fp16, (K,N) -> (N,K))
    wtrans<<<dim3(1536 / 32, 512 / 32), dim3(32, 8)>>>(qkvw, wq, 512, 1536);
    wtrans<<<dim3(512 / 32, 512 / 32),  dim3(32, 8)>>>(pw,   wp, 512, 512);
    wtrans<<<dim3(2048 / 32, 512 / 32), dim3(32, 8)>>>(f1w,  w1, 512, 2048);
    wtrans<<<dim3(512 / 32, 2048 / 32), dim3(32, 8)>>>(f2w,  w2, 2048, 512);

    // LN1
    ln_kernel<<<TOK / 32, 256>>>(x, n1g, n1b, img);
    // QKV GEMM -> fp32 row-major
    gemm_hmma<0><<<dim3(12, 256), 256>>>(img, wq, nullptr, nullptr, qkv, TOK, 1536, 512);
    // LePE then attention (accumulates onto att)
    lepe_kernel<<<512, 256>>>(qkv, l0w, l0b, l1w, l1b, att);
    attn_kernel<<<4096, 128>>>(qkv, att);
    // proj + bias + x residual -> xf (C,L) fp32
    gemm_hmma<1><<<dim3(4, 256), 256>>>(att, wp, pb, x, xf, TOK, 0, 512);
    // LN2
    ln_kernel<<<TOK / 32, 256>>>(xf, n2g, n2b, h2);
    // fc1 + bias + gelu -> mid fp16 row-major
    gemm_hmma<2><<<dim3(16, 256), 256>>>(h2, w1, f1b, nullptr, mid, TOK, 2048, 512);
    // fc2 + bias + xf residual -> out (C,L) fp32
    gemm_hmma<1><<<dim3(4, 256), 256>>>(mid, w2, f2b, xf, out, TOK, 0, 2048);
}

// round 7
// speedup vs baseline: 4.3664x; 1.2852x over previous
#include <cuda_runtime.h>
#include <cuda_fp16.h>
#include <math.h>
#include <stdint.h>

#define TOK 32768

// ======================= scratch (no cudaMalloc allowed) =======================
__device__ __half g_img[(size_t)TOK * 512];     // LN1 out, (L,C) row-major fp16
__device__ __half g_wq [(size_t)1536 * 512];    // qkv_w^T  (N,K) fp16
__device__ __half g_wp [(size_t)512 * 512];     // proj_w^T
__device__ __half g_w1 [(size_t)2048 * 512];    // fc1_w^T
__device__ __half g_w2 [(size_t)512 * 2048];    // fc2_w^T
__device__ __half g_qkvh[(size_t)TOK * 1536];   // (L,3C) fp16 row-major
__device__ __half g_att[(size_t)TOK * 512];     // lepe+attn out, (L,C) fp16
__device__ float  g_xf [(size_t)512 * TOK];     // (C,L) fp32 col-major
__device__ __half g_h2 [(size_t)TOK * 512];     // LN2 out fp16 (L,C)
__device__ __half g_mid[(size_t)TOK * 2048];    // gelu(fc1) fp16 (L,2048)

// ======================= PTX helpers (sm_80-level only) =======================
__device__ __forceinline__ uint32_t smem_u32(const void* p) {
    uint32_t a;
    asm("{ .reg .u64 t; cvta.to.shared.u64 t, %1; cvt.u32.u64 %0, t; }" : "=r"(a) : "l"(p));
    return a;
}
__device__ __forceinline__ void ldm4(uint32_t* r, uint32_t a) {
    asm volatile("ldmatrix.sync.aligned.m8n8.x4.shared.b16 {%0,%1,%2,%3}, [%4];"
        : "=r"(r[0]), "=r"(r[1]), "=r"(r[2]), "=r"(r[3]) : "r"(a));
}
__device__ __forceinline__ void mma16816(float* d, const uint32_t* a, const uint32_t* b) {
    asm volatile("mma.sync.aligned.m16n8k16.row.col.f32.f16.f16.f32 "
        "{%0,%1,%2,%3}, {%4,%5,%6,%7}, {%8,%9}, {%0,%1,%2,%3};"
        : "+f"(d[0]), "+f"(d[1]), "+f"(d[2]), "+f"(d[3])
        : "r"(a[0]), "r"(a[1]), "r"(a[2]), "r"(a[3]), "r"(b[0]), "r"(b[1]));
}
__device__ __forceinline__ uint32_t packh2(float a, float b) {
    __half2 h = __floats2half2_rn(a, b);
    return *(uint32_t*)&h;
}

// ======================= HMMA GEMM =======================
// C[M,N] = A[M,K](fp16 row-major) * Bw[N,K]^T (fp16, K contiguous per row)
// EPI 0: fp32 row-major out (ld=ldo)
// EPI 1: fp32 col-major out[n*M+m] = acc + bias[n] + res[n*M+m]
// EPI 2: fp16 row-major out = gelu(acc + bias[n]), ld=ldo
// EPI 3: fp16 row-major out = acc, ld=ldo
#define TSTR 40   // smem row stride in halves (80 B)
template<int EPI>
__global__ __launch_bounds__(256)
void gemm_hmma(const __half* __restrict__ A, const __half* __restrict__ Bw,
               const float* __restrict__ bias, const float* __restrict__ res,
               void* __restrict__ outp, int M, int ldo, int K)
{
    __shared__ __half sA[2][128 * TSTR];
    __shared__ __half sB[2][128 * TSTR];
    const int tid  = threadIdx.x;
    const int lane = tid & 31;
    const int warp = tid >> 5;
    const int wm = warp & 1;        // 2 warps along M
    const int wn = warp >> 1;       // 4 warps along N
    const int m0 = blockIdx.y * 128;
    const int n0 = blockIdx.x * 128;

    float acc[4][4][4];
#pragma unroll
    for (int i = 0; i < 4; i++)
#pragma unroll
        for (int j = 0; j < 4; j++)
#pragma unroll
            for (int k = 0; k < 4; k++) acc[i][j][k] = 0.f;

    const int chunks = K >> 5;           // K-chunk = 32
    const int grow = tid >> 2;           // 0..63  (with i*64 offset -> 0..127)
    const int gcol = (tid & 3) * 8;      // halves

    uint4 ra[2], rb[2];
#pragma unroll
    for (int i = 0; i < 2; i++) {
        int r = grow + i * 64;
        ra[i] = *(const uint4*)&A [(size_t)(m0 + r) * K + gcol];
        rb[i] = *(const uint4*)&Bw[(size_t)(n0 + r) * K + gcol];
    }
#pragma unroll
    for (int i = 0; i < 2; i++) {
        int r = grow + i * 64;
        *(uint4*)&sA[0][r * TSTR + gcol] = ra[i];
        *(uint4*)&sB[0][r * TSTR + gcol] = rb[i];
    }
    __syncthreads();

    for (int c = 0; c < chunks; c++) {
        const int buf = c & 1;
        if (c + 1 < chunks) {
            int koff = (c + 1) * 32;
#pragma unroll
            for (int i = 0; i < 2; i++) {
                int r = grow + i * 64;
                ra[i] = *(const uint4*)&A [(size_t)(m0 + r) * K + koff + gcol];
                rb[i] = *(const uint4*)&Bw[(size_t)(n0 + r) * K + koff + gcol];
            }
        }
        const uint32_t baseA = smem_u32(sA[buf]);
        const uint32_t baseB = smem_u32(sB[buf]);
#pragma unroll
        for (int kk = 0; kk < 2; kk++) {
            uint32_t af[4][4];
#pragma unroll
            for (int mt = 0; mt < 4; mt++) {
                int row = wm * 64 + mt * 16 + (lane & 15);
                int col = kk * 16 + ((lane >> 4) << 3);
                ldm4(af[mt], baseA + (uint32_t)(row * TSTR + col) * 2);
            }
            uint32_t bf[4][2];
#pragma unroll
            for (int pr = 0; pr < 2; pr++) {
                int row = wn * 32 + pr * 16 + ((lane >> 4) & 1) * 8 + (lane & 7);
                int col = kk * 16 + ((lane >> 3) & 1) * 8;
                uint32_t t4[4];
                ldm4(t4, baseB + (uint32_t)(row * TSTR + col) * 2);
                bf[pr * 2][0] = t4[0]; bf[pr * 2][1] = t4[1];
                bf[pr * 2 + 1][0] = t4[2]; bf[pr * 2 + 1][1] = t4[3];
            }
#pragma unroll
            for (int mt = 0; mt < 4; mt++)
#pragma unroll
                for (int nt = 0; nt < 4; nt++)
                    mma16816(acc[mt][nt], af[mt], bf[nt]);
        }
        __syncthreads();
        if (c + 1 < chunks) {
            const int nb = (c + 1) & 1;
#pragma unroll
            for (int i = 0; i < 2; i++) {
                int r = grow + i * 64;
                *(uint4*)&sA[nb][r * TSTR + gcol] = ra[i];
                *(uint4*)&sB[nb][r * TSTR + gcol] = rb[i];
            }
            __syncthreads();
        }
    }

    // ---------------- epilogue ----------------
#pragma unroll
    for (int mt = 0; mt < 4; mt++) {
        int r = m0 + wm * 64 + mt * 16 + (lane >> 2);
#pragma unroll
        for (int nt = 0; nt < 4; nt++) {
            int cN = n0 + wn * 32 + nt * 8 + 2 * (lane & 3);
            float v0 = acc[mt][nt][0], v1 = acc[mt][nt][1];
            float v2 = acc[mt][nt][2], v3 = acc[mt][nt][3];
            if (EPI == 1 || EPI == 2) {
                float b0 = __ldg(&bias[cN]), b1 = __ldg(&bias[cN + 1]);
                v0 += b0; v1 += b1; v2 += b0; v3 += b1;
            }
            if (EPI == 2) {
                v0 = 0.5f * v0 * (1.f + erff(v0 * 0.70710678118654752f));
                v1 = 0.5f * v1 * (1.f + erff(v1 * 0.70710678118654752f));
                v2 = 0.5f * v2 * (1.f + erff(v2 * 0.70710678118654752f));
                v3 = 0.5f * v3 * (1.f + erff(v3 * 0.70710678118654752f));
            }
            if (EPI == 1) {
                float* o = (float*)outp;
                size_t i00 = (size_t)cN * M + r;
                size_t i01 = (size_t)(cN + 1) * M + r;
                v0 += __ldg(&res[i00]);     v1 += __ldg(&res[i01]);
                v2 += __ldg(&res[i00 + 8]); v3 += __ldg(&res[i01 + 8]);
                o[i00] = v0; o[i01] = v1; o[i00 + 8] = v2; o[i01 + 8] = v3;
            } else if (EPI == 0) {
                float* o = (float*)outp;
                *(float2*)&o[(size_t)r * ldo + cN]       = make_float2(v0, v1);
                *(float2*)&o[(size_t)(r + 8) * ldo + cN] = make_float2(v2, v3);
            } else {
                __half* o = (__half*)outp;
                *(__half2*)&o[(size_t)r * ldo + cN]       = __floats2half2_rn(v0, v1);
                *(__half2*)&o[(size_t)(r + 8) * ldo + cN] = __floats2half2_rn(v2, v3);
            }
        }
    }
}

// ======================= weight transpose + fp16 convert =======================
__global__ void wtrans(const float* __restrict__ w, __half* __restrict__ wT, int K, int N)
{
    __shared__ float s[32][33];
    int n0 = blockIdx.x * 32, k0 = blockIdx.y * 32;
    int tx = threadIdx.x, ty = threadIdx.y;
    for (int i = ty; i < 32; i += 8) s[i][tx] = w[(size_t)(k0 + i) * N + n0 + tx];
    __syncthreads();
    for (int i = ty; i < 32; i += 8) wT[(size_t)(n0 + i) * K + k0 + tx] = __float2half(s[tx][i]);
}

// ======================= LN: (C,L) fp32 -> (L,C) fp16 (static smem) =======================
__global__ __launch_bounds__(256)
void ln_kernel(const float* __restrict__ in, const float* __restrict__ g,
               const float* __restrict__ b, __half* __restrict__ out)
{
    __shared__ __half stg[32 * 520];
    __shared__ float red[512];
    __shared__ float ms[32], rs[32];
    int tx = threadIdx.x & 31, ty = threadIdx.x >> 5;
    int tok = blockIdx.x * 32 + tx;
    float sum = 0.f, sq = 0.f;
    for (int c = ty; c < 512; c += 8) {
        float x = in[(size_t)c * TOK + tok];
        sum += x; sq += x * x;
    }
    red[ty * 32 + tx] = sum; red[256 + ty * 32 + tx] = sq;
    __syncthreads();
    if (ty == 0) {
        float s = 0.f, q = 0.f;
        for (int j = 0; j < 8; j++) { s += red[j * 32 + tx]; q += red[256 + j * 32 + tx]; }
        float mean = s * (1.f / 512.f);
        float var  = q * (1.f / 512.f) - mean * mean;
        ms[tx] = mean; rs[tx] = rsqrtf(var + 1e-5f);
    }
    __syncthreads();
    for (int c = ty; c < 512; c += 8) {
        float x = in[(size_t)c * TOK + tok];
        stg[tx * 520 + c] = __float2half((x - ms[tx]) * rs[tx] * g[c] + b[c]);
    }
    __syncthreads();
    size_t base = (size_t)blockIdx.x * 32 * 512;
#pragma unroll
    for (int i = 0; i < 8; i++) {
        int id = threadIdx.x + i * 256;
        int row = id >> 6, c8 = (id & 63) * 8;
        *(uint4*)&out[base + (size_t)row * 512 + c8] = *(uint4*)&stg[row * 520 + c8];
    }
}

// ======================= LePE (depthwise 3x3 per window, fp16 qkv) =======================
__global__ __launch_bounds__(256)
void lepe_kernel(const __half* __restrict__ qkv,
                 const float* __restrict__ w0, const float* __restrict__ b0,
                 const float* __restrict__ w1, const float* __restrict__ b1,
                 __half* __restrict__ att)
{
    int bw = blockIdx.x;
    int branch = bw >> 8;
    int widx = bw & 255;
    int d = widx >> 3, g = widx & 7;
    int c = threadIdx.x;

    const float* W  = branch ? w1 : w0;
    const float* Bv = branch ? b1 : b0;
    float w[9];
#pragma unroll
    for (int r = 0; r < 9; r++) w[r] = W[c * 9 + r];
    float bias = Bv[c];

    const int Hs = branch ? 4 : 32;
    const int Ws = branch ? 32 : 4;
    const int shift = branch ? 5 : 2;
    const int mask = Ws - 1;
    const size_t voff = 1024 + branch * 256 + c;

    for (int t = 0; t < 128; t++) {
        int i = t >> shift, j = t & mask;
        float acc = bias;
#pragma unroll
        for (int di = -1; di <= 1; di++) {
            int ii = i + di;
            if (ii < 0 || ii >= Hs) continue;
#pragma unroll
            for (int dj = -1; dj <= 1; dj++) {
                int jj = j + dj;
                if (jj < 0 || jj >= Ws) continue;
                int ll = (branch == 0) ? d * 1024 + ii * 32 + g * 4 + jj
                                       : d * 1024 + (g * 4 + ii) * 32 + jj;
                acc += w[(di + 1) * 3 + (dj + 1)] * __half2float(qkv[(size_t)ll * 1536 + voff]);
            }
        }
        int l = (branch == 0) ? d * 1024 + i * 32 + g * 4 + j
                              : d * 1024 + g * 128 + t;
        att[(size_t)l * 512 + branch * 256 + c] = __float2half(acc);
    }
}

// ======================= HMMA windowed attention =======================
// One block per (branch, window, head): 128 tokens x headdim 32.
// S = Q K^T (fp16 in, fp32 acc), P = exp(S*scale), O = P V (FA2 register reuse),
// O/rowsum accumulated onto att (which holds lepe).
__global__ __launch_bounds__(128)
void attn_hmma(const __half* __restrict__ qkv, __half* __restrict__ att)
{
    __shared__ __half qs[128 * 40];
    __shared__ __half ks[128 * 40];
    __shared__ __half vt[32 * 136];    // V transposed: [channel][token]
    const int tid = threadIdx.x;
    const int lane = tid & 31, warp = tid >> 5;
    const int bid = blockIdx.x;
    const int head = bid & 7;
    const int widx = (bid >> 3) & 255;
    const int branch = bid >> 11;
    const int d = widx >> 3, g = widx & 7;
    const int cc = branch * 256 + head * 32;

    // ---- load Q,K rows + V transposed (thread t = token row t in window) ----
    {
        int w = tid;
        int l = (branch == 0) ? d * 1024 + (w >> 2) * 32 + g * 4 + (w & 3)
                              : d * 1024 + g * 128 + w;
        const uint4* src = (const uint4*)&qkv[(size_t)l * 1536 + cc];
        uint4 qv[4], kv[4], vv[4];
#pragma unroll
        for (int i = 0; i < 4; i++) { qv[i] = src[i]; kv[i] = src[64 + i]; vv[i] = src[128 + i]; }
#pragma unroll
        for (int i = 0; i < 4; i++) {
            *(uint4*)&qs[w * 40 + i * 8] = qv[i];
            *(uint4*)&ks[w * 40 + i * 8] = kv[i];
        }
        const __half* vh = (const __half*)vv;
#pragma unroll
        for (int c = 0; c < 32; c++) vt[c * 136 + w] = vh[c];
    }
    __syncthreads();

    const uint32_t qb = smem_u32(qs);
    const uint32_t kb = smem_u32(ks);
    const uint32_t vb = smem_u32(vt);

    // Q fragments persist across chunks: warp covers rows [warp*32, warp*32+32)
    uint32_t aq[2][2][4];
#pragma unroll
    for (int mt = 0; mt < 2; mt++)
#pragma unroll
        for (int kk = 0; kk < 2; kk++) {
            int row = warp * 32 + mt * 16 + (lane & 15);
            int col = kk * 16 + ((lane >> 4) << 3);
            ldm4(aq[mt][kk], qb + (uint32_t)(row * 40 + col) * 2);
        }

    float oacc[2][4][4];
#pragma unroll
    for (int i = 0; i < 2; i++)
#pragma unroll
        for (int j = 0; j < 4; j++)
#pragma unroll
            for (int k = 0; k < 4; k++) oacc[i][j][k] = 0.f;
    float lsum[2][2] = {{0.f, 0.f}, {0.f, 0.f}};
    const float scale = 0.17677669529663687f;

#pragma unroll 1
    for (int ch = 0; ch < 2; ch++) {          // 64 key-columns per chunk
        float s[2][8][4];
#pragma unroll
        for (int i = 0; i < 2; i++)
#pragma unroll
            for (int j = 0; j < 8; j++)
#pragma unroll
                for (int k = 0; k < 4; k++) s[i][j][k] = 0.f;
        // ---- S = Q K^T ----
#pragma unroll
        for (int kk = 0; kk < 2; kk++) {
            uint32_t kf[8][2];
#pragma unroll
            for (int pg = 0; pg < 4; pg++) {
                int row = ch * 64 + pg * 16 + ((lane >> 4) & 1) * 8 + (lane & 7);
                int col = kk * 16 + ((lane >> 3) & 1) * 8;
                uint32_t t4[4];
                ldm4(t4, kb + (uint32_t)(row * 40 + col) * 2);
                kf[pg * 2][0] = t4[0]; kf[pg * 2][1] = t4[1];
                kf[pg * 2 + 1][0] = t4[2]; kf[pg * 2 + 1][1] = t4[3];
            }
#pragma unroll
            for (int mt = 0; mt < 2; mt++)
#pragma unroll
                for (int nt = 0; nt < 8; nt++)
                    mma16816(s[mt][nt], aq[mt][kk], kf[nt]);
        }
        // ---- P = exp(S*scale), convert to A-fragments for PV ----
        uint32_t pa[2][4][4];
#pragma unroll
        for (int mt = 0; mt < 2; mt++)
#pragma unroll
            for (int j = 0; j < 4; j++) {
                float e[8];
#pragma unroll
                for (int q2 = 0; q2 < 2; q2++)
#pragma unroll
                    for (int r4 = 0; r4 < 4; r4++)
                        e[q2 * 4 + r4] = __expf(s[mt][2 * j + q2][r4] * scale);
                lsum[mt][0] += e[0] + e[1] + e[4] + e[5];
                lsum[mt][1] += e[2] + e[3] + e[6] + e[7];
                pa[mt][j][0] = packh2(e[0], e[1]);
                pa[mt][j][1] = packh2(e[2], e[3]);
                pa[mt][j][2] = packh2(e[4], e[5]);
                pa[mt][j][3] = packh2(e[6], e[7]);
            }
        // ---- O += P V ----
#pragma unroll
        for (int j = 0; j < 4; j++) {
            uint32_t vf[4][2];
#pragma unroll
            for (int pg = 0; pg < 2; pg++) {
                int row = pg * 16 + ((lane >> 4) & 1) * 8 + (lane & 7);
                int col = ch * 64 + j * 16 + ((lane >> 3) & 1) * 8;
                uint32_t t4[4];
                ldm4(t4, vb + (uint32_t)(row * 136 + col) * 2);
                vf[pg * 2][0] = t4[0]; vf[pg * 2][1] = t4[1];
                vf[pg * 2 + 1][0] = t4[2]; vf[pg * 2 + 1][1] = t4[3];
            }
#pragma unroll
            for (int mt = 0; mt < 2; mt++)
#pragma unroll
                for (int nt = 0; nt < 4; nt++)
                    mma16816(oacc[mt][nt], pa[mt][j], vf[nt]);
        }
    }

    // ---- row-sum reduce across quad lanes, invert ----
#pragma unroll
    for (int mt = 0; mt < 2; mt++)
#pragma unroll
        for (int h = 0; h < 2; h++) {
            float v = lsum[mt][h];
            v += __shfl_xor_sync(0xffffffffu, v, 1);
            v += __shfl_xor_sync(0xffffffffu, v, 2);
            lsum[mt][h] = 1.f / v;
        }

    // ---- epilogue: att += O / rowsum (att holds lepe) ----
#pragma unroll
    for (int mt = 0; mt < 2; mt++) {
        int w0 = warp * 32 + mt * 16 + (lane >> 2);
#pragma unroll
        for (int h = 0; h < 2; h++) {
            int w = w0 + h * 8;
            int l = (branch == 0) ? d * 1024 + (w >> 2) * 32 + g * 4 + (w & 3)
                                  : d * 1024 + g * 128 + w;
            __half* ap = att + (size_t)l * 512 + cc;
            float inv = lsum[mt][h];
#pragma unroll
            for (int nt = 0; nt < 4; nt++) {
                int col = nt * 8 + 2 * (lane & 3);
                __half2 prev = *(__half2*)(ap + col);
                float2 pf = __half22float2(prev);
                *(__half2*)(ap + col) = __floats2half2_rn(
                    pf.x + oacc[mt][nt][h * 2 + 0] * inv,
                    pf.y + oacc[mt][nt][h * 2 + 1] * inv);
            }
        }
    }
}

// ======================= launch =======================
extern "C" void kernel_launch(void* const* d_in, const int* in_sizes, int n_in,
                              void* d_out, int out_size)
{
    const float* x    = (const float*)d_in[0];
    const float* n1g  = (const float*)d_in[1];
    const float* n1b  = (const float*)d_in[2];
    const float* qkvw = (const float*)d_in[3];
    const float* l0w  = (const float*)d_in[4];
    const float* l0b  = (const float*)d_in[5];
    const float* l1w  = (const float*)d_in[6];
    const float* l1b  = (const float*)d_in[7];
    const float* pw   = (const float*)d_in[8];
    const float* pb   = (const float*)d_in[9];
    const float* n2g  = (const float*)d_in[10];
    const float* n2b  = (const float*)d_in[11];
    const float* f1w  = (const float*)d_in[12];
    const float* f1b  = (const float*)d_in[13];
    const float* f2w  = (const float*)d_in[14];
    const float* f2b  = (const float*)d_in[15];
    float* out = (float*)d_out;

    __half *img, *wq, *wp, *w1, *w2, *qkv, *att, *h2, *mid;
    float *xf;
    cudaGetSymbolAddress((void**)&img, g_img);
    cudaGetSymbolAddress((void**)&wq,  g_wq);
    cudaGetSymbolAddress((void**)&wp,  g_wp);
    cudaGetSymbolAddress((void**)&w1,  g_w1);
    cudaGetSymbolAddress((void**)&w2,  g_w2);
    cudaGetSymbolAddress((void**)&qkv, g_qkvh);
    cudaGetSymbolAddress((void**)&att, g_att);
    cudaGetSymbolAddress((void**)&xf,  g_xf);
    cudaGetSymbolAddress((void**)&h2,  g_h2);
    cudaGetSymbolAddress((void**)&mid, g_mid);

    // weight transposes (fp32 -> fp16, (K,N) -> (N,K))
    wtrans<<<dim3(1536 / 32, 512 / 32), dim3(32, 8)>>>(qkvw, wq, 512, 1536);
    wtrans<<<dim3(512 / 32, 512 / 32),  dim3(32, 8)>>>(pw,   wp, 512, 512);
    wtrans<<<dim3(2048 / 32, 512 / 32), dim3(32, 8)>>>(f1w,  w1, 512, 2048);
    wtrans<<<dim3(512 / 32, 2048 / 32), dim3(32, 8)>>>(f2w,  w2, 2048, 512);

    // LN1
    ln_kernel<<<TOK / 32, 256>>>(x, n1g, n1b, img);
    // QKV GEMM -> fp16 row-major
    gemm_hmma<3><<<dim3(12, 256), 256>>>(img, wq, nullptr, nullptr, qkv, TOK, 1536, 512);
    // LePE then attention (accumulates onto att)
    lepe_kernel<<<512, 256>>>(qkv, l0w, l0b, l1w, l1b, att);
    attn_hmma<<<4096, 128>>>(qkv, att);
    // proj + bias + x residual -> xf (C,L) fp32
    gemm_hmma<1><<<dim3(4, 256), 256>>>(att, wp, pb, x, xf, TOK, 0, 512);
    // LN2
    ln_kernel<<<TOK / 32, 256>>>(xf, n2g, n2b, h2);
    // fc1 + bias + gelu -> mid fp16 row-major
    gemm_hmma<2><<<dim3(16, 256), 256>>>(h2, w1, f1b, nullptr, mid, TOK, 2048, 512);
    // fc2 + bias + xf residual -> out (C,L) fp32
    gemm_hmma<1><<<dim3(4, 256), 256>>>(mid, w2, f2b, xf, out, TOK, 0, 2048);
}

// round 8
// speedup vs baseline: 5.0287x; 1.1517x over previous
#include <cuda_runtime.h>
#include <cuda_fp16.h>
#include <math.h>
#include <stdint.h>

#define TOK 32768

// ======================= scratch (no cudaMalloc allowed) =======================
__device__ __half g_img[(size_t)TOK * 512];     // LN1 out, (L,C) row-major fp16
__device__ __half g_wq [(size_t)1536 * 512];    // qkv_w^T  (N,K) fp16
__device__ __half g_wp [(size_t)512 * 512];     // proj_w^T
__device__ __half g_w1 [(size_t)2048 * 512];    // fc1_w^T
__device__ __half g_w2 [(size_t)512 * 2048];    // fc2_w^T
__device__ __half g_qkvh[(size_t)TOK * 1536];   // (L,3C) fp16 row-major
__device__ __half g_att[(size_t)TOK * 512];     // lepe+attn out, (L,C) fp16
__device__ float  g_xf [(size_t)512 * TOK];     // (C,L) fp32 col-major
__device__ __half g_h2 [(size_t)TOK * 512];     // LN2 out fp16 (L,C)
__device__ __half g_mid[(size_t)TOK * 2048];    // gelu(fc1) fp16 (L,2048)

// ======================= PTX helpers (sm_80-level only) =======================
__device__ __forceinline__ uint32_t smem_u32(const void* p) {
    uint32_t a;
    asm("{ .reg .u64 t; cvta.to.shared.u64 t, %1; cvt.u32.u64 %0, t; }" : "=r"(a) : "l"(p));
    return a;
}
__device__ __forceinline__ void ldm4(uint32_t* r, uint32_t a) {
    asm volatile("ldmatrix.sync.aligned.m8n8.x4.shared.b16 {%0,%1,%2,%3}, [%4];"
        : "=r"(r[0]), "=r"(r[1]), "=r"(r[2]), "=r"(r[3]) : "r"(a));
}
__device__ __forceinline__ void mma16816(float* d, const uint32_t* a, const uint32_t* b) {
    asm volatile("mma.sync.aligned.m16n8k16.row.col.f32.f16.f16.f32 "
        "{%0,%1,%2,%3}, {%4,%5,%6,%7}, {%8,%9}, {%0,%1,%2,%3};"
        : "+f"(d[0]), "+f"(d[1]), "+f"(d[2]), "+f"(d[3])
        : "r"(a[0]), "r"(a[1]), "r"(a[2]), "r"(a[3]), "r"(b[0]), "r"(b[1]));
}
__device__ __forceinline__ uint32_t packh2(float a, float b) {
    __half2 h = __floats2half2_rn(a, b);
    return *(uint32_t*)&h;
}
#define CP_ASYNC16(dst, src) \
    asm volatile("cp.async.cg.shared.global [%0], [%1], 16;" :: "r"(dst), "l"(src))
#define CP_COMMIT() asm volatile("cp.async.commit_group;" ::: "memory")
#define CP_WAIT1()  asm volatile("cp.async.wait_group 1;" ::: "memory")
#define CP_WAIT0()  asm volatile("cp.async.wait_group 0;" ::: "memory")

// ======================= HMMA GEMM (cp.async 3-stage) =======================
// C[M,N] = A[M,K](fp16 row-major) * Bw[N,K]^T (fp16, K contiguous per row)
// EPI 0: fp32 row-major out (ld=ldo)
// EPI 1: fp32 col-major out[n*M+m] = acc + bias[n] + res[n*M+m]
// EPI 2: fp16 row-major out = gelu(acc + bias[n]), ld=ldo
// EPI 3: fp16 row-major out = acc, ld=ldo
#define TSTR 40                 // smem row stride in halves (80 B)
#define GSTG (128 * TSTR)       // halves per stage per matrix
#define GEMM_SMEM_BYTES (6 * GSTG * 2)   // 3 stages x (A+B) = 61440 B

extern __shared__ __half smem_g[];

template<int EPI>
__global__ __launch_bounds__(256)
void gemm_hmma(const __half* __restrict__ A, const __half* __restrict__ Bw,
               const float* __restrict__ bias, const float* __restrict__ res,
               void* __restrict__ outp, int M, int ldo, int K)
{
    const int tid  = threadIdx.x;
    const int lane = tid & 31;
    const int warp = tid >> 5;
    const int wm = warp & 1;        // 2 warps along M
    const int wn = warp >> 1;       // 4 warps along N
    const int m0 = blockIdx.y * 128;
    const int n0 = blockIdx.x * 128;

    float acc[4][4][4];
#pragma unroll
    for (int i = 0; i < 4; i++)
#pragma unroll
        for (int j = 0; j < 4; j++)
#pragma unroll
            for (int k = 0; k < 4; k++) acc[i][j][k] = 0.f;

    const int chunks = K >> 5;           // K-chunk = 32
    const int grow = tid >> 2;           // 0..63
    const int gcol = (tid & 3) * 8;      // halves
    const uint32_t smb = smem_u32(smem_g);

    // issue stage c into buffer c%3
    auto issue = [&](int c) {
        int buf = c - (c / 3) * 3;
        uint32_t sa = smb + (uint32_t)(buf * GSTG) * 2;
        uint32_t sb = smb + (uint32_t)((3 + buf) * GSTG) * 2;
#pragma unroll
        for (int i = 0; i < 2; i++) {
            int r = grow + i * 64;
            CP_ASYNC16(sa + (uint32_t)(r * TSTR + gcol) * 2,
                       &A [(size_t)(m0 + r) * K + c * 32 + gcol]);
            CP_ASYNC16(sb + (uint32_t)(r * TSTR + gcol) * 2,
                       &Bw[(size_t)(n0 + r) * K + c * 32 + gcol]);
        }
    };

    issue(0); CP_COMMIT();
    issue(1); CP_COMMIT();

    for (int c = 0; c < chunks; c++) {
        CP_WAIT1();
        __syncthreads();
        if (c + 2 < chunks) issue(c + 2);
        CP_COMMIT();

        const int buf = c - (c / 3) * 3;
        const uint32_t baseA = smb + (uint32_t)(buf * GSTG) * 2;
        const uint32_t baseB = smb + (uint32_t)((3 + buf) * GSTG) * 2;
#pragma unroll
        for (int kk = 0; kk < 2; kk++) {
            uint32_t af[4][4];
#pragma unroll
            for (int mt = 0; mt < 4; mt++) {
                int row = wm * 64 + mt * 16 + (lane & 15);
                int col = kk * 16 + ((lane >> 4) << 3);
                ldm4(af[mt], baseA + (uint32_t)(row * TSTR + col) * 2);
            }
            uint32_t bf[4][2];
#pragma unroll
            for (int pr = 0; pr < 2; pr++) {
                int row = wn * 32 + pr * 16 + ((lane >> 4) & 1) * 8 + (lane & 7);
                int col = kk * 16 + ((lane >> 3) & 1) * 8;
                uint32_t t4[4];
                ldm4(t4, baseB + (uint32_t)(row * TSTR + col) * 2);
                bf[pr * 2][0] = t4[0]; bf[pr * 2][1] = t4[1];
                bf[pr * 2 + 1][0] = t4[2]; bf[pr * 2 + 1][1] = t4[3];
            }
#pragma unroll
            for (int mt = 0; mt < 4; mt++)
#pragma unroll
                for (int nt = 0; nt < 4; nt++)
                    mma16816(acc[mt][nt], af[mt], bf[nt]);
        }
    }
    CP_WAIT0();

    // ---------------- epilogue ----------------
#pragma unroll
    for (int mt = 0; mt < 4; mt++) {
        int r = m0 + wm * 64 + mt * 16 + (lane >> 2);
#pragma unroll
        for (int nt = 0; nt < 4; nt++) {
            int cN = n0 + wn * 32 + nt * 8 + 2 * (lane & 3);
            float v0 = acc[mt][nt][0], v1 = acc[mt][nt][1];
            float v2 = acc[mt][nt][2], v3 = acc[mt][nt][3];
            if (EPI == 1 || EPI == 2) {
                float b0 = __ldg(&bias[cN]), b1 = __ldg(&bias[cN + 1]);
                v0 += b0; v1 += b1; v2 += b0; v3 += b1;
            }
            if (EPI == 2) {
                v0 = 0.5f * v0 * (1.f + erff(v0 * 0.70710678118654752f));
                v1 = 0.5f * v1 * (1.f + erff(v1 * 0.70710678118654752f));
                v2 = 0.5f * v2 * (1.f + erff(v2 * 0.70710678118654752f));
                v3 = 0.5f * v3 * (1.f + erff(v3 * 0.70710678118654752f));
            }
            if (EPI == 1) {
                float* o = (float*)outp;
                size_t i00 = (size_t)cN * M + r;
                size_t i01 = (size_t)(cN + 1) * M + r;
                v0 += __ldg(&res[i00]);     v1 += __ldg(&res[i01]);
                v2 += __ldg(&res[i00 + 8]); v3 += __ldg(&res[i01 + 8]);
                o[i00] = v0; o[i01] = v1; o[i00 + 8] = v2; o[i01 + 8] = v3;
            } else if (EPI == 0) {
                float* o = (float*)outp;
                *(float2*)&o[(size_t)r * ldo + cN]       = make_float2(v0, v1);
                *(float2*)&o[(size_t)(r + 8) * ldo + cN] = make_float2(v2, v3);
            } else {
                __half* o = (__half*)outp;
                *(__half2*)&o[(size_t)r * ldo + cN]       = __floats2half2_rn(v0, v1);
                *(__half2*)&o[(size_t)(r + 8) * ldo + cN] = __floats2half2_rn(v2, v3);
            }
        }
    }
}

// ======================= weight transpose + fp16 convert =======================
__global__ void wtrans(const float* __restrict__ w, __half* __restrict__ wT, int K, int N)
{
    __shared__ float s[32][33];
    int n0 = blockIdx.x * 32, k0 = blockIdx.y * 32;
    int tx = threadIdx.x, ty = threadIdx.y;
    for (int i = ty; i < 32; i += 8) s[i][tx] = w[(size_t)(k0 + i) * N + n0 + tx];
    __syncthreads();
    for (int i = ty; i < 32; i += 8) wT[(size_t)(n0 + i) * K + k0 + tx] = __float2half(s[tx][i]);
}

// ======================= LN: (C,L) fp32 -> (L,C) fp16 (static smem) =======================
__global__ __launch_bounds__(256)
void ln_kernel(const float* __restrict__ in, const float* __restrict__ g,
               const float* __restrict__ b, __half* __restrict__ out)
{
    __shared__ __half stg[32 * 520];
    __shared__ float red[512];
    __shared__ float ms[32], rs[32];
    int tx = threadIdx.x & 31, ty = threadIdx.x >> 5;
    int tok = blockIdx.x * 32 + tx;
    float sum = 0.f, sq = 0.f;
    for (int c = ty; c < 512; c += 8) {
        float x = in[(size_t)c * TOK + tok];
        sum += x; sq += x * x;
    }
    red[ty * 32 + tx] = sum; red[256 + ty * 32 + tx] = sq;
    __syncthreads();
    if (ty == 0) {
        float s = 0.f, q = 0.f;
        for (int j = 0; j < 8; j++) { s += red[j * 32 + tx]; q += red[256 + j * 32 + tx]; }
        float mean = s * (1.f / 512.f);
        float var  = q * (1.f / 512.f) - mean * mean;
        ms[tx] = mean; rs[tx] = rsqrtf(var + 1e-5f);
    }
    __syncthreads();
    for (int c = ty; c < 512; c += 8) {
        float x = in[(size_t)c * TOK + tok];
        stg[tx * 520 + c] = __float2half((x - ms[tx]) * rs[tx] * g[c] + b[c]);
    }
    __syncthreads();
    size_t base = (size_t)blockIdx.x * 32 * 512;
#pragma unroll
    for (int i = 0; i < 8; i++) {
        int id = threadIdx.x + i * 256;
        int row = id >> 6, c8 = (id & 63) * 8;
        *(uint4*)&out[base + (size_t)row * 512 + c8] = *(uint4*)&stg[row * 520 + c8];
    }
}

// ======================= HMMA windowed attention + fused LePE =======================
// One block per (branch, window, head): 128 tokens x headdim 32.
// lepe computed in-block from the V tile already in smem; epilogue is a pure store.
__global__ __launch_bounds__(128)
void attn_hmma(const __half* __restrict__ qkv, __half* __restrict__ att,
               const float* __restrict__ w0, const float* __restrict__ b0,
               const float* __restrict__ w1, const float* __restrict__ b1)
{
    __shared__ __half qs[128 * 40];
    __shared__ __half ks[128 * 40];
    __shared__ __half vt[32 * 136];    // V transposed: [channel][token]
    __shared__ __half lp[128 * 34];    // lepe: [token][channel]
    __shared__ float swt[32 * 9];
    __shared__ float sbv[32];
    const int tid = threadIdx.x;
    const int lane = tid & 31, warp = tid >> 5;
    const int bid = blockIdx.x;
    const int head = bid & 7;
    const int widx = (bid >> 3) & 255;
    const int branch = bid >> 11;
    const int d = widx >> 3, g = widx & 7;
    const int cc = branch * 256 + head * 32;

    // ---- load conv weights for this head's 32 channels ----
    if (tid < 32) {
        const float* W  = branch ? w1 : w0;
        const float* Bv = branch ? b1 : b0;
        int chn = head * 32 + tid;
#pragma unroll
        for (int r = 0; r < 9; r++) swt[tid * 9 + r] = W[chn * 9 + r];
        sbv[tid] = Bv[chn];
    }

    // ---- load Q,K rows + V transposed (thread t = token row t in window) ----
    {
        int w = tid;
        int l = (branch == 0) ? d * 1024 + (w >> 2) * 32 + g * 4 + (w & 3)
                              : d * 1024 + g * 128 + w;
        const uint4* src = (const uint4*)&qkv[(size_t)l * 1536 + cc];
        uint4 qv[4], kv[4], vv[4];
#pragma unroll
        for (int i = 0; i < 4; i++) { qv[i] = src[i]; kv[i] = src[64 + i]; vv[i] = src[128 + i]; }
#pragma unroll
        for (int i = 0; i < 4; i++) {
            *(uint4*)&qs[w * 40 + i * 8] = qv[i];
            *(uint4*)&ks[w * 40 + i * 8] = kv[i];
        }
        const __half* vh = (const __half*)vv;
#pragma unroll
        for (int c = 0; c < 32; c++) vt[c * 136 + w] = vh[c];
    }
    __syncthreads();

    // ---- fused LePE: depthwise 3x3 over this window's V (in smem) ----
    {
        int w = tid;
        int i, j, Hs, Ws;
        if (branch == 0) { i = w >> 2; j = w & 3;  Hs = 32; Ws = 4; }
        else             { i = w >> 5; j = w & 31; Hs = 4;  Ws = 32; }
        float acc[32];
#pragma unroll
        for (int c = 0; c < 32; c++) acc[c] = sbv[c];
        for (int di = -1; di <= 1; di++) {
            int ii = i + di;
            if (ii < 0 || ii >= Hs) continue;
            for (int dj = -1; dj <= 1; dj++) {
                int jj = j + dj;
                if (jj < 0 || jj >= Ws) continue;
                int wp = (branch == 0) ? ((ii << 2) | jj) : ((ii << 5) | jj);
                int tap = (di + 1) * 3 + (dj + 1);
#pragma unroll
                for (int c = 0; c < 32; c++)
                    acc[c] += swt[c * 9 + tap] * __half2float(vt[c * 136 + wp]);
            }
        }
#pragma unroll
        for (int c = 0; c < 32; c++) lp[w * 34 + c] = __float2half(acc[c]);
    }
    __syncthreads();

    const uint32_t qb = smem_u32(qs);
    const uint32_t kb = smem_u32(ks);
    const uint32_t vb = smem_u32(vt);

    // Q fragments persist across chunks: warp covers rows [warp*32, warp*32+32)
    uint32_t aq[2][2][4];
#pragma unroll
    for (int mt = 0; mt < 2; mt++)
#pragma unroll
        for (int kk = 0; kk < 2; kk++) {
            int row = warp * 32 + mt * 16 + (lane & 15);
            int col = kk * 16 + ((lane >> 4) << 3);
            ldm4(aq[mt][kk], qb + (uint32_t)(row * 40 + col) * 2);
        }

    float oacc[2][4][4];
#pragma unroll
    for (int i = 0; i < 2; i++)
#pragma unroll
        for (int j = 0; j < 4; j++)
#pragma unroll
            for (int k = 0; k < 4; k++) oacc[i][j][k] = 0.f;
    float lsum[2][2] = {{0.f, 0.f}, {0.f, 0.f}};
    const float scale = 0.17677669529663687f;

#pragma unroll 1
    for (int ch = 0; ch < 2; ch++) {          // 64 key-columns per chunk
        float s[2][8][4];
#pragma unroll
        for (int i = 0; i < 2; i++)
#pragma unroll
            for (int j = 0; j < 8; j++)
#pragma unroll
                for (int k = 0; k < 4; k++) s[i][j][k] = 0.f;
        // ---- S = Q K^T ----
#pragma unroll
        for (int kk = 0; kk < 2; kk++) {
            uint32_t kf[8][2];
#pragma unroll
            for (int pg = 0; pg < 4; pg++) {
                int row = ch * 64 + pg * 16 + ((lane >> 4) & 1) * 8 + (lane & 7);
                int col = kk * 16 + ((lane >> 3) & 1) * 8;
                uint32_t t4[4];
                ldm4(t4, kb + (uint32_t)(row * 40 + col) * 2);
                kf[pg * 2][0] = t4[0]; kf[pg * 2][1] = t4[1];
                kf[pg * 2 + 1][0] = t4[2]; kf[pg * 2 + 1][1] = t4[3];
            }
#pragma unroll
            for (int mt = 0; mt < 2; mt++)
#pragma unroll
                for (int nt = 0; nt < 8; nt++)
                    mma16816(s[mt][nt], aq[mt][kk], kf[nt]);
        }
        // ---- P = exp(S*scale), convert to A-fragments for PV ----
        uint32_t pa[2][4][4];
#pragma unroll
        for (int mt = 0; mt < 2; mt++)
#pragma unroll
            for (int j = 0; j < 4; j++) {
                float e[8];
#pragma unroll
                for (int q2 = 0; q2 < 2; q2++)
#pragma unroll
                    for (int r4 = 0; r4 < 4; r4++)
                        e[q2 * 4 + r4] = __expf(s[mt][2 * j + q2][r4] * scale);
                lsum[mt][0] += e[0] + e[1] + e[4] + e[5];
                lsum[mt][1] += e[2] + e[3] + e[6] + e[7];
                pa[mt][j][0] = packh2(e[0], e[1]);
                pa[mt][j][1] = packh2(e[2], e[3]);
                pa[mt][j][2] = packh2(e[4], e[5]);
                pa[mt][j][3] = packh2(e[6], e[7]);
            }
        // ---- O += P V ----
#pragma unroll
        for (int j = 0; j < 4; j++) {
            uint32_t vf[4][2];
#pragma unroll
            for (int pg = 0; pg < 2; pg++) {
                int row = pg * 16 + ((lane >> 4) & 1) * 8 + (lane & 7);
                int col = ch * 64 + j * 16 + ((lane >> 3) & 1) * 8;
                uint32_t t4[4];
                ldm4(t4, vb + (uint32_t)(row * 136 + col) * 2);
                vf[pg * 2][0] = t4[0]; vf[pg * 2][1] = t4[1];
                vf[pg * 2 + 1][0] = t4[2]; vf[pg * 2 + 1][1] = t4[3];
            }
#pragma unroll
            for (int mt = 0; mt < 2; mt++)
#pragma unroll
                for (int nt = 0; nt < 4; nt++)
                    mma16816(oacc[mt][nt], pa[mt][j], vf[nt]);
        }
    }

    // ---- row-sum reduce across quad lanes, invert ----
#pragma unroll
    for (int mt = 0; mt < 2; mt++)
#pragma unroll
        for (int h = 0; h < 2; h++) {
            float v = lsum[mt][h];
            v += __shfl_xor_sync(0xffffffffu, v, 1);
            v += __shfl_xor_sync(0xffffffffu, v, 2);
            lsum[mt][h] = 1.f / v;
        }

    // ---- epilogue: att = lepe + O / rowsum (pure store) ----
#pragma unroll
    for (int mt = 0; mt < 2; mt++) {
        int w0r = warp * 32 + mt * 16 + (lane >> 2);
#pragma unroll
        for (int h = 0; h < 2; h++) {
            int w = w0r + h * 8;
            int l = (branch == 0) ? d * 1024 + (w >> 2) * 32 + g * 4 + (w & 3)
                                  : d * 1024 + g * 128 + w;
            __half* ap = att + (size_t)l * 512 + cc;
            float inv = lsum[mt][h];
#pragma unroll
            for (int nt = 0; nt < 4; nt++) {
                int col = nt * 8 + 2 * (lane & 3);
                float lep0 = __half2float(lp[w * 34 + col]);
                float lep1 = __half2float(lp[w * 34 + col + 1]);
                *(__half2*)(ap + col) = __floats2half2_rn(
                    lep0 + oacc[mt][nt][h * 2 + 0] * inv,
                    lep1 + oacc[mt][nt][h * 2 + 1] * inv);
            }
        }
    }
}

// ======================= launch =======================
extern "C" void kernel_launch(void* const* d_in, const int* in_sizes, int n_in,
                              void* d_out, int out_size)
{
    const float* x    = (const float*)d_in[0];
    const float* n1g  = (const float*)d_in[1];
    const float* n1b  = (const float*)d_in[2];
    const float* qkvw = (const float*)d_in[3];
    const float* l0w  = (const float*)d_in[4];
    const float* l0b  = (const float*)d_in[5];
    const float* l1w  = (const float*)d_in[6];
    const float* l1b  = (const float*)d_in[7];
    const float* pw   = (const float*)d_in[8];
    const float* pb   = (const float*)d_in[9];
    const float* n2g  = (const float*)d_in[10];
    const float* n2b  = (const float*)d_in[11];
    const float* f1w  = (const float*)d_in[12];
    const float* f1b  = (const float*)d_in[13];
    const float* f2w  = (const float*)d_in[14];
    const float* f2b  = (const float*)d_in[15];
    float* out = (float*)d_out;

    __half *img, *wq, *wp, *w1, *w2, *qkv, *att, *h2, *mid;
    float *xf;
    cudaGetSymbolAddress((void**)&img, g_img);
    cudaGetSymbolAddress((void**)&wq,  g_wq);
    cudaGetSymbolAddress((void**)&wp,  g_wp);
    cudaGetSymbolAddress((void**)&w1,  g_w1);
    cudaGetSymbolAddress((void**)&w2,  g_w2);
    cudaGetSymbolAddress((void**)&qkv, g_qkvh);
    cudaGetSymbolAddress((void**)&att, g_att);
    cudaGetSymbolAddress((void**)&xf,  g_xf);
    cudaGetSymbolAddress((void**)&h2,  g_h2);
    cudaGetSymbolAddress((void**)&mid, g_mid);

    cudaFuncSetAttribute(gemm_hmma<1>, cudaFuncAttributeMaxDynamicSharedMemorySize, GEMM_SMEM_BYTES);
    cudaFuncSetAttribute(gemm_hmma<2>, cudaFuncAttributeMaxDynamicSharedMemorySize, GEMM_SMEM_BYTES);
    cudaFuncSetAttribute(gemm_hmma<3>, cudaFuncAttributeMaxDynamicSharedMemorySize, GEMM_SMEM_BYTES);

    // weight transposes (fp32 -> fp16, (K,N) -> (N,K))
    wtrans<<<dim3(1536 / 32, 512 / 32), dim3(32, 8)>>>(qkvw, wq, 512, 1536);
    wtrans<<<dim3(512 / 32, 512 / 32),  dim3(32, 8)>>>(pw,   wp, 512, 512);
    wtrans<<<dim3(2048 / 32, 512 / 32), dim3(32, 8)>>>(f1w,  w1, 512, 2048);
    wtrans<<<dim3(512 / 32, 2048 / 32), dim3(32, 8)>>>(f2w,  w2, 2048, 512);

    // LN1
    ln_kernel<<<TOK / 32, 256>>>(x, n1g, n1b, img);
    // QKV GEMM -> fp16 row-major
    gemm_hmma<3><<<dim3(12, 256), 256, GEMM_SMEM_BYTES>>>(img, wq, nullptr, nullptr, qkv, TOK, 1536, 512);
    // attention with fused LePE -> att (pure store)
    attn_hmma<<<4096, 128>>>(qkv, att, l0w, l0b, l1w, l1b);
    // proj + bias + x residual -> xf (C,L) fp32
    gemm_hmma<1><<<dim3(4, 256), 256, GEMM_SMEM_BYTES>>>(att, wp, pb, x, xf, TOK, 0, 512);
    // LN2
    ln_kernel<<<TOK / 32, 256>>>(xf, n2g, n2b, h2);
    // fc1 + bias + gelu -> mid fp16 row-major
    gemm_hmma<2><<<dim3(16, 256), 256, GEMM_SMEM_BYTES>>>(h2, w1, f1b, nullptr, mid, TOK, 2048, 512);
    // fc2 + bias + xf residual -> out (C,L) fp32
    gemm_hmma<1><<<dim3(4, 256), 256, GEMM_SMEM_BYTES>>>(mid, w2, f2b, xf, out, TOK, 0, 2048);
}

// round 10
// speedup vs baseline: 5.3379x; 1.0615x over previous
#include <cuda_runtime.h>
#include <cuda_fp16.h>
#include <math.h>
#include <stdint.h>

#define TOK 32768

// ======================= scratch (no cudaMalloc allowed) =======================
__device__ __half g_img[(size_t)TOK * 512];     // LN1 out, (L,C) row-major fp16
__device__ __half g_wq [(size_t)1536 * 512];    // qkv_w^T  (N,K) fp16
__device__ __half g_wp [(size_t)512 * 512];     // proj_w^T
__device__ __half g_w1 [(size_t)2048 * 512];    // fc1_w^T
__device__ __half g_w2 [(size_t)512 * 2048];    // fc2_w^T
__device__ __half g_qkvh[(size_t)TOK * 1536];   // (L,3C) fp16 row-major
__device__ __half g_att[(size_t)TOK * 512];     // lepe+attn out, (L,C) fp16
__device__ float  g_xf [(size_t)512 * TOK];     // (C,L) fp32 col-major
__device__ __half g_h2 [(size_t)TOK * 512];     // LN2 out fp16 (L,C)
__device__ __half g_mid[(size_t)TOK * 2048];    // gelu(fc1) fp16 (L,2048)

// ======================= PTX helpers (sm_80-level only) =======================
__device__ __forceinline__ uint32_t smem_u32(const void* p) {
    uint32_t a;
    asm("{ .reg .u64 t; cvta.to.shared.u64 t, %1; cvt.u32.u64 %0, t; }" : "=r"(a) : "l"(p));
    return a;
}
__device__ __forceinline__ void ldm4(uint32_t* r, uint32_t a) {
    asm volatile("ldmatrix.sync.aligned.m8n8.x4.shared.b16 {%0,%1,%2,%3}, [%4];"
        : "=r"(r[0]), "=r"(r[1]), "=r"(r[2]), "=r"(r[3]) : "r"(a));
}
__device__ __forceinline__ void mma16816(float* d, const uint32_t* a, const uint32_t* b) {
    asm volatile("mma.sync.aligned.m16n8k16.row.col.f32.f16.f16.f32 "
        "{%0,%1,%2,%3}, {%4,%5,%6,%7}, {%8,%9}, {%0,%1,%2,%3};"
        : "+f"(d[0]), "+f"(d[1]), "+f"(d[2]), "+f"(d[3])
        : "r"(a[0]), "r"(a[1]), "r"(a[2]), "r"(a[3]), "r"(b[0]), "r"(b[1]));
}
__device__ __forceinline__ uint32_t packh2(float a, float b) {
    __half2 h = __floats2half2_rn(a, b);
    return *(uint32_t*)&h;
}
#define CP_ASYNC16(dst, src) \
    asm volatile("cp.async.cg.shared.global [%0], [%1], 16;" :: "r"(dst), "l"(src))
#define CP_COMMIT() asm volatile("cp.async.commit_group;" ::: "memory")
#define CP_WAIT1()  asm volatile("cp.async.wait_group 1;" ::: "memory")
#define CP_WAIT0()  asm volatile("cp.async.wait_group 0;" ::: "memory")

extern __shared__ char smem_raw[];

// ======================= HMMA GEMM (cp.async 3-stage, K-chunk 64) =======================
// C[M,N] = A[M,K](fp16 row-major) * Bw[N,K]^T (fp16, K contiguous per row)
// EPI 1: fp32 col-major out[n*M+m] = acc + bias[n] + res[n*M+m]
// EPI 2: fp16 row-major out = gelu(acc + bias[n]), ld=ldo
// EPI 3: fp16 row-major out = acc, ld=ldo
#define TSTR 72                 // smem row stride in halves (144 B)
#define GSTG (128 * TSTR)       // halves per stage per matrix
#define GEMM_SMEM_BYTES (6 * GSTG * 2)   // 3 stages x (A+B) = 110592 B

template<int EPI>
__global__ __launch_bounds__(256)
void gemm_hmma(const __half* __restrict__ A, const __half* __restrict__ Bw,
               const float* __restrict__ bias, const float* __restrict__ res,
               void* __restrict__ outp, int M, int ldo, int K)
{
    const int tid  = threadIdx.x;
    const int lane = tid & 31;
    const int warp = tid >> 5;
    const int wm = warp & 1;        // 2 warps along M
    const int wn = warp >> 1;       // 4 warps along N
    const int m0 = blockIdx.y * 128;
    const int n0 = blockIdx.x * 128;

    float acc[4][4][4];
#pragma unroll
    for (int i = 0; i < 4; i++)
#pragma unroll
        for (int j = 0; j < 4; j++)
#pragma unroll
            for (int k = 0; k < 4; k++) acc[i][j][k] = 0.f;

    const int chunks = K >> 6;           // K-chunk = 64
    const int grow = tid >> 3;           // 0..31 (4 groups of 32 rows)
    const int gcol = (tid & 7) * 8;      // halves: 8 lanes x 16B = full 128B row
    const uint32_t smb = smem_u32(smem_raw);

    auto issue = [&](int c) {
        int buf = c - (c / 3) * 3;
        uint32_t sa = smb + (uint32_t)(buf * GSTG) * 2;
        uint32_t sb = smb + (uint32_t)((3 + buf) * GSTG) * 2;
#pragma unroll
        for (int i = 0; i < 4; i++) {
            int r = grow + i * 32;
            CP_ASYNC16(sa + (uint32_t)(r * TSTR + gcol) * 2,
                       &A [(size_t)(m0 + r) * K + c * 64 + gcol]);
            CP_ASYNC16(sb + (uint32_t)(r * TSTR + gcol) * 2,
                       &Bw[(size_t)(n0 + r) * K + c * 64 + gcol]);
        }
    };

    issue(0); CP_COMMIT();
    issue(1); CP_COMMIT();

    for (int c = 0; c < chunks; c++) {
        CP_WAIT1();
        __syncthreads();
        if (c + 2 < chunks) issue(c + 2);
        CP_COMMIT();

        const int buf = c - (c / 3) * 3;
        const uint32_t baseA = smb + (uint32_t)(buf * GSTG) * 2;
        const uint32_t baseB = smb + (uint32_t)((3 + buf) * GSTG) * 2;
#pragma unroll
        for (int kk = 0; kk < 4; kk++) {
            uint32_t af[4][4];
#pragma unroll
            for (int mt = 0; mt < 4; mt++) {
                int row = wm * 64 + mt * 16 + (lane & 15);
                int col = kk * 16 + ((lane >> 4) << 3);
                ldm4(af[mt], baseA + (uint32_t)(row * TSTR + col) * 2);
            }
            uint32_t bf[4][2];
#pragma unroll
            for (int pr = 0; pr < 2; pr++) {
                int row = wn * 32 + pr * 16 + ((lane >> 4) & 1) * 8 + (lane & 7);
                int col = kk * 16 + ((lane >> 3) & 1) * 8;
                uint32_t t4[4];
                ldm4(t4, baseB + (uint32_t)(row * TSTR + col) * 2);
                bf[pr * 2][0] = t4[0]; bf[pr * 2][1] = t4[1];
                bf[pr * 2 + 1][0] = t4[2]; bf[pr * 2 + 1][1] = t4[3];
            }
#pragma unroll
            for (int mt = 0; mt < 4; mt++)
#pragma unroll
                for (int nt = 0; nt < 4; nt++)
                    mma16816(acc[mt][nt], af[mt], bf[nt]);
        }
    }
    CP_WAIT0();

    // ---------------- epilogue ----------------
#pragma unroll
    for (int mt = 0; mt < 4; mt++) {
        int r = m0 + wm * 64 + mt * 16 + (lane >> 2);
#pragma unroll
        for (int nt = 0; nt < 4; nt++) {
            int cN = n0 + wn * 32 + nt * 8 + 2 * (lane & 3);
            float v0 = acc[mt][nt][0], v1 = acc[mt][nt][1];
            float v2 = acc[mt][nt][2], v3 = acc[mt][nt][3];
            if (EPI == 1 || EPI == 2) {
                float b0 = __ldg(&bias[cN]), b1 = __ldg(&bias[cN + 1]);
                v0 += b0; v1 += b1; v2 += b0; v3 += b1;
            }
            if (EPI == 2) {
                v0 = 0.5f * v0 * (1.f + erff(v0 * 0.70710678118654752f));
                v1 = 0.5f * v1 * (1.f + erff(v1 * 0.70710678118654752f));
                v2 = 0.5f * v2 * (1.f + erff(v2 * 0.70710678118654752f));
                v3 = 0.5f * v3 * (1.f + erff(v3 * 0.70710678118654752f));
            }
            if (EPI == 1) {
                float* o = (float*)outp;
                size_t i00 = (size_t)cN * M + r;
                size_t i01 = (size_t)(cN + 1) * M + r;
                v0 += __ldg(&res[i00]);     v1 += __ldg(&res[i01]);
                v2 += __ldg(&res[i00 + 8]); v3 += __ldg(&res[i01 + 8]);
                o[i00] = v0; o[i01] = v1; o[i00 + 8] = v2; o[i01 + 8] = v3;
            } else {
                __half* o = (__half*)outp;
                *(__half2*)&o[(size_t)r * ldo + cN]       = __floats2half2_rn(v0, v1);
                *(__half2*)&o[(size_t)(r + 8) * ldo + cN] = __floats2half2_rn(v2, v3);
            }
        }
    }
}

// ======================= merged weight transpose + fp16 convert =======================
__global__ void wtrans_all(const float* __restrict__ qkvw, __half* __restrict__ wq,
                           const float* __restrict__ pw,   __half* __restrict__ wp,
                           const float* __restrict__ f1w,  __half* __restrict__ w1,
                           const float* __restrict__ f2w,  __half* __restrict__ w2)
{
    __shared__ float s[32][33];
    int b = blockIdx.x;
    const float* w; __half* wT; int K, N, t;
    if (b < 768)       { w = qkvw; wT = wq; K = 512;  N = 1536; t = b; }
    else if (b < 1024) { w = pw;   wT = wp; K = 512;  N = 512;  t = b - 768; }
    else if (b < 2048) { w = f1w;  wT = w1; K = 512;  N = 2048; t = b - 1024; }
    else               { w = f2w;  wT = w2; K = 2048; N = 512;  t = b - 2048; }
    int tx0 = N >> 5;
    int n0 = (t % tx0) * 32, k0 = (t / tx0) * 32;
    int tx = threadIdx.x, ty = threadIdx.y;
    for (int i = ty; i < 32; i += 8) s[i][tx] = w[(size_t)(k0 + i) * N + n0 + tx];
    __syncthreads();
    for (int i = ty; i < 32; i += 8) wT[(size_t)(n0 + i) * K + k0 + tx] = __float2half(s[tx][i]);
}

// ======================= LN: (C,L) fp32 -> (L,C) fp16, single gmem pass =======================
#define LNSTR 517
#define LN_SMEM_BYTES (32 * LNSTR * 4)
__global__ __launch_bounds__(256)
void ln_kernel(const float* __restrict__ in, const float* __restrict__ g,
               const float* __restrict__ b, __half* __restrict__ out)
{
    float* stg = (float*)smem_raw;     // [32][LNSTR]
    __shared__ float red[512];
    __shared__ float ms[32], rs[32];
    int tx = threadIdx.x & 31, ty = threadIdx.x >> 5;
    int tok = blockIdx.x * 32 + tx;
    float sum = 0.f, sq = 0.f;
    for (int c = ty; c < 512; c += 8) {
        float x = in[(size_t)c * TOK + tok];
        stg[tx * LNSTR + c] = x;
        sum += x; sq += x * x;
    }
    red[ty * 32 + tx] = sum; red[256 + ty * 32 + tx] = sq;
    __syncthreads();
    if (ty == 0) {
        float s = 0.f, q = 0.f;
        for (int j = 0; j < 8; j++) { s += red[j * 32 + tx]; q += red[256 + j * 32 + tx]; }
        float mean = s * (1.f / 512.f);
        float var  = q * (1.f / 512.f) - mean * mean;
        ms[tx] = mean; rs[tx] = rsqrtf(var + 1e-5f);
    }
    __syncthreads();
    size_t base = (size_t)blockIdx.x * 32 * 512;
#pragma unroll
    for (int i = 0; i < 8; i++) {
        int id = threadIdx.x + i * 256;
        int row = id >> 6, c8 = (id & 63) * 8;
        float mean = ms[row], rstd = rs[row];
        __half h[8];
#pragma unroll
        for (int j = 0; j < 8; j++) {
            int c = c8 + j;
            h[j] = __float2half((stg[row * LNSTR + c] - mean) * rstd * g[c] + b[c]);
        }
        *(uint4*)&out[base + (size_t)row * 512 + c8] = *(uint4*)h;
    }
}

// ======================= HMMA windowed attention + fused LePE =======================
__global__ __launch_bounds__(128)
void attn_hmma(const __half* __restrict__ qkv, __half* __restrict__ att,
               const float* __restrict__ w0, const float* __restrict__ b0,
               const float* __restrict__ w1, const float* __restrict__ b1)
{
    __shared__ __half qs[128 * 40];
    __shared__ __half ks[128 * 40];
    __shared__ __half vt[32 * 136];    // V transposed: [channel][token]
    __shared__ __half lp[128 * 34];    // lepe: [token][channel]
    __shared__ float swt[32 * 9];
    __shared__ float sbv[32];
    const int tid = threadIdx.x;
    const int lane = tid & 31, warp = tid >> 5;
    const int bid = blockIdx.x;
    const int head = bid & 7;
    const int widx = (bid >> 3) & 255;
    const int branch = bid >> 11;
    const int d = widx >> 3, g = widx & 7;
    const int cc = branch * 256 + head * 32;

    if (tid < 32) {
        const float* W  = branch ? w1 : w0;
        const float* Bv = branch ? b1 : b0;
        int chn = head * 32 + tid;
#pragma unroll
        for (int r = 0; r < 9; r++) swt[tid * 9 + r] = W[chn * 9 + r];
        sbv[tid] = Bv[chn];
    }

    {
        int w = tid;
        int l = (branch == 0) ? d * 1024 + (w >> 2) * 32 + g * 4 + (w & 3)
                              : d * 1024 + g * 128 + w;
        const uint4* src = (const uint4*)&qkv[(size_t)l * 1536 + cc];
        uint4 qv[4], kv[4], vv[4];
#pragma unroll
        for (int i = 0; i < 4; i++) { qv[i] = src[i]; kv[i] = src[64 + i]; vv[i] = src[128 + i]; }
#pragma unroll
        for (int i = 0; i < 4; i++) {
            *(uint4*)&qs[w * 40 + i * 8] = qv[i];
            *(uint4*)&ks[w * 40 + i * 8] = kv[i];
        }
        const __half* vh = (const __half*)vv;
#pragma unroll
        for (int c = 0; c < 32; c++) vt[c * 136 + w] = vh[c];
    }
    __syncthreads();

    {
        int w = tid;
        int i, j, Hs, Ws;
        if (branch == 0) { i = w >> 2; j = w & 3;  Hs = 32; Ws = 4; }
        else             { i = w >> 5; j = w & 31; Hs = 4;  Ws = 32; }
        float acc[32];
#pragma unroll
        for (int c = 0; c < 32; c++) acc[c] = sbv[c];
        for (int di = -1; di <= 1; di++) {
            int ii = i + di;
            if (ii < 0 || ii >= Hs) continue;
            for (int dj = -1; dj <= 1; dj++) {
                int jj = j + dj;
                if (jj < 0 || jj >= Ws) continue;
                int wp = (branch == 0) ? ((ii << 2) | jj) : ((ii << 5) | jj);
                int tap = (di + 1) * 3 + (dj + 1);
#pragma unroll
                for (int c = 0; c < 32; c++)
                    acc[c] += swt[c * 9 + tap] * __half2float(vt[c * 136 + wp]);
            }
        }
#pragma unroll
        for (int c = 0; c < 32; c++) lp[w * 34 + c] = __float2half(acc[c]);
    }
    __syncthreads();

    const uint32_t qb = smem_u32(qs);
    const uint32_t kb = smem_u32(ks);
    const uint32_t vb = smem_u32(vt);

    uint32_t aq[2][2][4];
#pragma unroll
    for (int mt = 0; mt < 2; mt++)
#pragma unroll
        for (int kk = 0; kk < 2; kk++) {
            int row = warp * 32 + mt * 16 + (lane & 15);
            int col = kk * 16 + ((lane >> 4) << 3);
            ldm4(aq[mt][kk], qb + (uint32_t)(row * 40 + col) * 2);
        }

    float oacc[2][4][4];
#pragma unroll
    for (int i = 0; i < 2; i++)
#pragma unroll
        for (int j = 0; j < 4; j++)
#pragma unroll
            for (int k = 0; k < 4; k++) oacc[i][j][k] = 0.f;
    float lsum[2][2] = {{0.f, 0.f}, {0.f, 0.f}};
    const float scale = 0.17677669529663687f;

#pragma unroll 1
    for (int ch = 0; ch < 2; ch++) {
        float s[2][8][4];
#pragma unroll
        for (int i = 0; i < 2; i++)
#pragma unroll
            for (int j = 0; j < 8; j++)
#pragma unroll
                for (int k = 0; k < 4; k++) s[i][j][k] = 0.f;
#pragma unroll
        for (int kk = 0; kk < 2; kk++) {
            uint32_t kf[8][2];
#pragma unroll
            for (int pg = 0; pg < 4; pg++) {
                int row = ch * 64 + pg * 16 + ((lane >> 4) & 1) * 8 + (lane & 7);
                int col = kk * 16 + ((lane >> 3) & 1) * 8;
                uint32_t t4[4];
                ldm4(t4, kb + (uint32_t)(row * 40 + col) * 2);
                kf[pg * 2][0] = t4[0]; kf[pg * 2][1] = t4[1];
                kf[pg * 2 + 1][0] = t4[2]; kf[pg * 2 + 1][1] = t4[3];
            }
#pragma unroll
            for (int mt = 0; mt < 2; mt++)
#pragma unroll
                for (int nt = 0; nt < 8; nt++)
                    mma16816(s[mt][nt], aq[mt][kk], kf[nt]);
        }
        uint32_t pa[2][4][4];
#pragma unroll
        for (int mt = 0; mt < 2; mt++)
#pragma unroll
            for (int j = 0; j < 4; j++) {
                float e[8];
#pragma unroll
                for (int q2 = 0; q2 < 2; q2++)
#pragma unroll
                    for (int r4 = 0; r4 < 4; r4++)
                        e[q2 * 4 + r4] = __expf(s[mt][2 * j + q2][r4] * scale);
                lsum[mt][0] += e[0] + e[1] + e[4] + e[5];
                lsum[mt][1] += e[2] + e[3] + e[6] + e[7];
                pa[mt][j][0] = packh2(e[0], e[1]);
                pa[mt][j][1] = packh2(e[2], e[3]);
                pa[mt][j][2] = packh2(e[4], e[5]);
                pa[mt][j][3] = packh2(e[6], e[7]);
            }
#pragma unroll
        for (int j = 0; j < 4; j++) {
            uint32_t vf[4][2];
#pragma unroll
            for (int pg = 0; pg < 2; pg++) {
                int row = pg * 16 + ((lane >> 4) & 1) * 8 + (lane & 7);
                int col = ch * 64 + j * 16 + ((lane >> 3) & 1) * 8;
                uint32_t t4[4];
                ldm4(t4, vb + (uint32_t)(row * 136 + col) * 2);
                vf[pg * 2][0] = t4[0]; vf[pg * 2][1] = t4[1];
                vf[pg * 2 + 1][0] = t4[2]; vf[pg * 2 + 1][1] = t4[3];
            }
#pragma unroll
            for (int mt = 0; mt < 2; mt++)
#pragma unroll
                for (int nt = 0; nt < 4; nt++)
                    mma16816(oacc[mt][nt], pa[mt][j], vf[nt]);
        }
    }

#pragma unroll
    for (int mt = 0; mt < 2; mt++)
#pragma unroll
        for (int h = 0; h < 2; h++) {
            float v = lsum[mt][h];
            v += __shfl_xor_sync(0xffffffffu, v, 1);
            v += __shfl_xor_sync(0xffffffffu, v, 2);
            lsum[mt][h] = 1.f / v;
        }

#pragma unroll
    for (int mt = 0; mt < 2; mt++) {
        int w0r = warp * 32 + mt * 16 + (lane >> 2);
#pragma unroll
        for (int h = 0; h < 2; h++) {
            int w = w0r + h * 8;
            int l = (branch == 0) ? d * 1024 + (w >> 2) * 32 + g * 4 + (w & 3)
                                  : d * 1024 + g * 128 + w;
            __half* ap = att + (size_t)l * 512 + cc;
            float inv = lsum[mt][h];
#pragma unroll
            for (int nt = 0; nt < 4; nt++) {
                int col = nt * 8 + 2 * (lane & 3);
                float lep0 = __half2float(lp[w * 34 + col]);
                float lep1 = __half2float(lp[w * 34 + col + 1]);
                *(__half2*)(ap + col) = __floats2half2_rn(
                    lep0 + oacc[mt][nt][h * 2 + 0] * inv,
                    lep1 + oacc[mt][nt][h * 2 + 1] * inv);
            }
        }
    }
}

// ======================= launch =======================
extern "C" void kernel_launch(void* const* d_in, const int* in_sizes, int n_in,
                              void* d_out, int out_size)
{
    const float* x    = (const float*)d_in[0];
    const float* n1g  = (const float*)d_in[1];
    const float* n1b  = (const float*)d_in[2];
    const float* qkvw = (const float*)d_in[3];
    const float* l0w  = (const float*)d_in[4];
    const float* l0b  = (const float*)d_in[5];
    const float* l1w  = (const float*)d_in[6];
    const float* l1b  = (const float*)d_in[7];
    const float* pw   = (const float*)d_in[8];
    const float* pb   = (const float*)d_in[9];
    const float* n2g  = (const float*)d_in[10];
    const float* n2b  = (const float*)d_in[11];
    const float* f1w  = (const float*)d_in[12];
    const float* f1b  = (const float*)d_in[13];
    const float* f2w  = (const float*)d_in[14];
    const float* f2b  = (const float*)d_in[15];
    float* out = (float*)d_out;

    __half *img, *wq, *wp, *w1, *w2, *qkv, *att, *h2, *mid;
    float *xf;
    cudaGetSymbolAddress((void**)&img, g_img);
    cudaGetSymbolAddress((void**)&wq,  g_wq);
    cudaGetSymbolAddress((void**)&wp,  g_wp);
    cudaGetSymbolAddress((void**)&w1,  g_w1);
    cudaGetSymbolAddress((void**)&w2,  g_w2);
    cudaGetSymbolAddress((void**)&qkv, g_qkvh);
    cudaGetSymbolAddress((void**)&att, g_att);
    cudaGetSymbolAddress((void**)&xf,  g_xf);
    cudaGetSymbolAddress((void**)&h2,  g_h2);
    cudaGetSymbolAddress((void**)&mid, g_mid);

    cudaFuncSetAttribute(gemm_hmma<1>, cudaFuncAttributeMaxDynamicSharedMemorySize, GEMM_SMEM_BYTES);
    cudaFuncSetAttribute(gemm_hmma<2>, cudaFuncAttributeMaxDynamicSharedMemorySize, GEMM_SMEM_BYTES);
    cudaFuncSetAttribute(gemm_hmma<3>, cudaFuncAttributeMaxDynamicSharedMemorySize, GEMM_SMEM_BYTES);
    cudaFuncSetAttribute(ln_kernel,    cudaFuncAttributeMaxDynamicSharedMemorySize, LN_SMEM_BYTES);

    // merged weight transposes (fp32 -> fp16, (K,N) -> (N,K))
    wtrans_all<<<3072, dim3(32, 8)>>>(qkvw, wq, pw, wp, f1w, w1, f2w, w2);

    // LN1
    ln_kernel<<<TOK / 32, 256, LN_SMEM_BYTES>>>(x, n1g, n1b, img);
    // QKV GEMM -> fp16 row-major
    gemm_hmma<3><<<dim3(12, 256), 256, GEMM_SMEM_BYTES>>>(img, wq, nullptr, nullptr, qkv, TOK, 1536, 512);
    // attention with fused LePE -> att (pure store)
    attn_hmma<<<4096, 128>>>(qkv, att, l0w, l0b, l1w, l1b);
    // proj + bias + x residual -> xf (C,L) fp32
    gemm_hmma<1><<<dim3(4, 256), 256, GEMM_SMEM_BYTES>>>(att, wp, pb, x, xf, TOK, 0, 512);
    // LN2
    ln_kernel<<<TOK / 32, 256, LN_SMEM_BYTES>>>(xf, n2g, n2b, h2);
    // fc1 + bias + gelu -> mid fp16 row-major
    gemm_hmma<2><<<dim3(16, 256), 256, GEMM_SMEM_BYTES>>>(h2, w1, f1b, nullptr, mid, TOK, 2048, 512);
    // fc2 + bias + xf residual -> out (C,L) fp32
    gemm_hmma<1><<<dim3(4, 256), 256, GEMM_SMEM_BYTES>>>(mid, w2, f2b, xf, out, TOK, 0, 2048);
}

// round 12
// speedup vs baseline: 5.3967x; 1.0110x over previous
#include <cuda_runtime.h>
#include <cuda_fp16.h>
#include <math.h>
#include <stdint.h>

#define TOK 32768

// ======================= scratch (no cudaMalloc allowed) =======================
__device__ __half g_img[(size_t)TOK * 512];     // LN1 out, (L,C) row-major fp16
__device__ __half g_wq [(size_t)1536 * 512];    // qkv_w^T  (N,K) fp16
__device__ __half g_wp [(size_t)512 * 512];     // proj_w^T
__device__ __half g_w1 [(size_t)2048 * 512];    // fc1_w^T
__device__ __half g_w2 [(size_t)512 * 2048];    // fc2_w^T
__device__ __half g_qkvh[(size_t)TOK * 1536];   // (L,3C) fp16 row-major
__device__ __half g_att[(size_t)TOK * 512];     // lepe+attn out, (L,C) fp16
__device__ float  g_xf [(size_t)512 * TOK];     // (C,L) fp32 col-major
__device__ __half g_h2 [(size_t)TOK * 512];     // LN2 out fp16 (L,C)
__device__ __half g_mid[(size_t)TOK * 2048];    // gelu(fc1) fp16 (L,2048)

// ======================= PTX helpers (sm_80-level only) =======================
__device__ __forceinline__ uint32_t smem_u32(const void* p) {
    uint32_t a;
    asm("{ .reg .u64 t; cvta.to.shared.u64 t, %1; cvt.u32.u64 %0, t; }" : "=r"(a) : "l"(p));
    return a;
}
__device__ __forceinline__ void ldm4(uint32_t* r, uint32_t a) {
    asm volatile("ldmatrix.sync.aligned.m8n8.x4.shared.b16 {%0,%1,%2,%3}, [%4];"
        : "=r"(r[0]), "=r"(r[1]), "=r"(r[2]), "=r"(r[3]) : "r"(a));
}
__device__ __forceinline__ void mma16816(float* d, const uint32_t* a, const uint32_t* b) {
    asm volatile("mma.sync.aligned.m16n8k16.row.col.f32.f16.f16.f32 "
        "{%0,%1,%2,%3}, {%4,%5,%6,%7}, {%8,%9}, {%0,%1,%2,%3};"
        : "+f"(d[0]), "+f"(d[1]), "+f"(d[2]), "+f"(d[3])
        : "r"(a[0]), "r"(a[1]), "r"(a[2]), "r"(a[3]), "r"(b[0]), "r"(b[1]));
}
__device__ __forceinline__ uint32_t packh2(float a, float b) {
    __half2 h = __floats2half2_rn(a, b);
    return *(uint32_t*)&h;
}
#define CP_ASYNC16(dst, src) \
    asm volatile("cp.async.cg.shared.global [%0], [%1], 16;" :: "r"(dst), "l"(src))
#define CP_COMMIT() asm volatile("cp.async.commit_group;" ::: "memory")
#define CP_WAIT1()  asm volatile("cp.async.wait_group 1;" ::: "memory")
#define CP_WAIT0()  asm volatile("cp.async.wait_group 0;" ::: "memory")

extern __shared__ char smem_raw[];

// ======================= HMMA GEMM (cp.async 3-stage, K-chunk 64) =======================
// C[M,N] = A[M,K](fp16 row-major) * Bw[N,K]^T (fp16, K contiguous per row)
// EPI 1: fp32 col-major out[n*M+m] = acc + bias[n] + res[n*M+m]
// EPI 2: fp16 row-major out = gelu(acc + bias[n]), ld=ldo
// EPI 3: fp16 row-major out = acc, ld=ldo
#define TSTR 72                 // smem row stride in halves (144 B)
#define GSTG (128 * TSTR)       // halves per stage per matrix
#define GEMM_SMEM_BYTES (6 * GSTG * 2)   // 3 stages x (A+B) = 110592 B

template<int EPI>
__global__ __launch_bounds__(256)
void gemm_hmma(const __half* __restrict__ A, const __half* __restrict__ Bw,
               const float* __restrict__ bias, const float* __restrict__ res,
               void* __restrict__ outp, int M, int ldo, int K)
{
    const int tid  = threadIdx.x;
    const int lane = tid & 31;
    const int warp = tid >> 5;
    const int wm = warp & 1;        // 2 warps along M
    const int wn = warp >> 1;       // 4 warps along N
    const int m0 = blockIdx.y * 128;
    const int n0 = blockIdx.x * 128;

    float acc[4][4][4];
#pragma unroll
    for (int i = 0; i < 4; i++)
#pragma unroll
        for (int j = 0; j < 4; j++)
#pragma unroll
            for (int k = 0; k < 4; k++) acc[i][j][k] = 0.f;

    const int chunks = K >> 6;           // K-chunk = 64
    const int grow = tid >> 3;           // 0..31 (4 groups of 32 rows)
    const int gcol = (tid & 7) * 8;      // halves: 8 lanes x 16B = full 128B row
    const uint32_t smb = smem_u32(smem_raw);

    auto issue = [&](int c) {
        int buf = c - (c / 3) * 3;
        uint32_t sa = smb + (uint32_t)(buf * GSTG) * 2;
        uint32_t sb = smb + (uint32_t)((3 + buf) * GSTG) * 2;
#pragma unroll
        for (int i = 0; i < 4; i++) {
            int r = grow + i * 32;
            CP_ASYNC16(sa + (uint32_t)(r * TSTR + gcol) * 2,
                       &A [(size_t)(m0 + r) * K + c * 64 + gcol]);
            CP_ASYNC16(sb + (uint32_t)(r * TSTR + gcol) * 2,
                       &Bw[(size_t)(n0 + r) * K + c * 64 + gcol]);
        }
    };

    issue(0); CP_COMMIT();
    issue(1); CP_COMMIT();

    for (int c = 0; c < chunks; c++) {
        CP_WAIT1();
        __syncthreads();
        if (c + 2 < chunks) issue(c + 2);
        CP_COMMIT();

        const int buf = c - (c / 3) * 3;
        const uint32_t baseA = smb + (uint32_t)(buf * GSTG) * 2;
        const uint32_t baseB = smb + (uint32_t)((3 + buf) * GSTG) * 2;
#pragma unroll
        for (int kk = 0; kk < 4; kk++) {
            uint32_t af[4][4];
#pragma unroll
            for (int mt = 0; mt < 4; mt++) {
                int row = wm * 64 + mt * 16 + (lane & 15);
                int col = kk * 16 + ((lane >> 4) << 3);
                ldm4(af[mt], baseA + (uint32_t)(row * TSTR + col) * 2);
            }
            uint32_t bf[4][2];
#pragma unroll
            for (int pr = 0; pr < 2; pr++) {
                int row = wn * 32 + pr * 16 + ((lane >> 4) & 1) * 8 + (lane & 7);
                int col = kk * 16 + ((lane >> 3) & 1) * 8;
                uint32_t t4[4];
                ldm4(t4, baseB + (uint32_t)(row * TSTR + col) * 2);
                bf[pr * 2][0] = t4[0]; bf[pr * 2][1] = t4[1];
                bf[pr * 2 + 1][0] = t4[2]; bf[pr * 2 + 1][1] = t4[3];
            }
#pragma unroll
            for (int mt = 0; mt < 4; mt++)
#pragma unroll
                for (int nt = 0; nt < 4; nt++)
                    mma16816(acc[mt][nt], af[mt], bf[nt]);
        }
    }
    CP_WAIT0();

    // ---------------- epilogue ----------------
#pragma unroll
    for (int mt = 0; mt < 4; mt++) {
        int r = m0 + wm * 64 + mt * 16 + (lane >> 2);
#pragma unroll
        for (int nt = 0; nt < 4; nt++) {
            int cN = n0 + wn * 32 + nt * 8 + 2 * (lane & 3);
            float v0 = acc[mt][nt][0], v1 = acc[mt][nt][1];
            float v2 = acc[mt][nt][2], v3 = acc[mt][nt][3];
            if (EPI == 1 || EPI == 2) {
                float b0 = __ldg(&bias[cN]), b1 = __ldg(&bias[cN + 1]);
                v0 += b0; v1 += b1; v2 += b0; v3 += b1;
            }
            if (EPI == 2) {
                v0 = 0.5f * v0 * (1.f + erff(v0 * 0.70710678118654752f));
                v1 = 0.5f * v1 * (1.f + erff(v1 * 0.70710678118654752f));
                v2 = 0.5f * v2 * (1.f + erff(v2 * 0.70710678118654752f));
                v3 = 0.5f * v3 * (1.f + erff(v3 * 0.70710678118654752f));
            }
            if (EPI == 1) {
                float* o = (float*)outp;
                size_t i00 = (size_t)cN * M + r;
                size_t i01 = (size_t)(cN + 1) * M + r;
                v0 += __ldg(&res[i00]);     v1 += __ldg(&res[i01]);
                v2 += __ldg(&res[i00 + 8]); v3 += __ldg(&res[i01 + 8]);
                o[i00] = v0; o[i01] = v1; o[i00 + 8] = v2; o[i01 + 8] = v3;
            } else {
                __half* o = (__half*)outp;
                *(__half2*)&o[(size_t)r * ldo + cN]       = __floats2half2_rn(v0, v1);
                *(__half2*)&o[(size_t)(r + 8) * ldo + cN] = __floats2half2_rn(v2, v3);
            }
        }
    }
}

// ======================= merged weight transpose + fp16 convert =======================
__global__ void wtrans_all(const float* __restrict__ qkvw, __half* __restrict__ wq,
                           const float* __restrict__ pw,   __half* __restrict__ wp,
                           const float* __restrict__ f1w,  __half* __restrict__ w1,
                           const float* __restrict__ f2w,  __half* __restrict__ w2)
{
    __shared__ float s[32][33];
    int b = blockIdx.x;
    const float* w; __half* wT; int K, N, t;
    if (b < 768)       { w = qkvw; wT = wq; K = 512;  N = 1536; t = b; }
    else if (b < 1024) { w = pw;   wT = wp; K = 512;  N = 512;  t = b - 768; }
    else if (b < 2048) { w = f1w;  wT = w1; K = 512;  N = 2048; t = b - 1024; }
    else               { w = f2w;  wT = w2; K = 2048; N = 512;  t = b - 2048; }
    int tx0 = N >> 5;
    int n0 = (t % tx0) * 32, k0 = (t / tx0) * 32;
    int tx = threadIdx.x, ty = threadIdx.y;
    for (int i = ty; i < 32; i += 8) s[i][tx] = w[(size_t)(k0 + i) * N + n0 + tx];
    __syncthreads();
    for (int i = ty; i < 32; i += 8) wT[(size_t)(n0 + i) * K + k0 + tx] = __float2half(s[tx][i]);
}

// ======================= LN: (C,L) fp32 -> (L,C) fp16, single gmem pass =======================
#define LNSTR 517
#define LN_SMEM_BYTES (32 * LNSTR * 4)
__global__ __launch_bounds__(256)
void ln_kernel(const float* __restrict__ in, const float* __restrict__ g,
               const float* __restrict__ b, __half* __restrict__ out)
{
    float* stg = (float*)smem_raw;     // [32][LNSTR]
    __shared__ float red[512];
    __shared__ float ms[32], rs[32];
    int tx = threadIdx.x & 31, ty = threadIdx.x >> 5;
    int tok = blockIdx.x * 32 + tx;
    float sum = 0.f, sq = 0.f;
    for (int c = ty; c < 512; c += 8) {
        float x = in[(size_t)c * TOK + tok];
        stg[tx * LNSTR + c] = x;
        sum += x; sq += x * x;
    }
    red[ty * 32 + tx] = sum; red[256 + ty * 32 + tx] = sq;
    __syncthreads();
    if (ty == 0) {
        float s = 0.f, q = 0.f;
        for (int j = 0; j < 8; j++) { s += red[j * 32 + tx]; q += red[256 + j * 32 + tx]; }
        float mean = s * (1.f / 512.f);
        float var  = q * (1.f / 512.f) - mean * mean;
        ms[tx] = mean; rs[tx] = rsqrtf(var + 1e-5f);
    }
    __syncthreads();
    size_t base = (size_t)blockIdx.x * 32 * 512;
#pragma unroll
    for (int i = 0; i < 8; i++) {
        int id = threadIdx.x + i * 256;
        int row = id >> 6, c8 = (id & 63) * 8;
        float mean = ms[row], rstd = rs[row];
        __half h[8];
#pragma unroll
        for (int j = 0; j < 8; j++) {
            int c = c8 + j;
            h[j] = __float2half((stg[row * LNSTR + c] - mean) * rstd * g[c] + b[c]);
        }
        *(uint4*)&out[base + (size_t)row * 512 + c8] = *(uint4*)h;
    }
}

// ======================= HMMA windowed attention + fused LePE =======================
// exp via ex2.approx.f16x2 (half the MUFU ops); lepe conv in half2 (half the LDS).
__global__ __launch_bounds__(128)
void attn_hmma(const __half* __restrict__ qkv, __half* __restrict__ att,
               const float* __restrict__ w0, const float* __restrict__ b0,
               const float* __restrict__ w1, const float* __restrict__ b1)
{
    __shared__ __half qs[128 * 40];
    __shared__ __half ks[128 * 40];
    __shared__ __half vt[32 * 136];    // V transposed: [channel][token] (for PV mma)
    __shared__ __half vs2[128 * 34];   // V token-major: [token][channel] (for lepe)
    __shared__ __half lp[128 * 34];    // lepe: [token][channel]
    __shared__ __half2 swt2[144];      // conv weights [tap][chpair]
    __shared__ float sbv[32];
    const int tid = threadIdx.x;
    const int lane = tid & 31, warp = tid >> 5;
    const int bid = blockIdx.x;
    const int head = bid & 7;
    const int widx = (bid >> 3) & 255;
    const int branch = bid >> 11;
    const int d = widx >> 3, g = widx & 7;
    const int cc = branch * 256 + head * 32;

    // ---- conv weights: half2 per channel pair, [tap][pair] ----
    {
        const float* W  = branch ? w1 : w0;
        for (int idx = tid; idx < 144; idx += 128) {
            int tap = idx >> 4, p = idx & 15;
            int ch0 = head * 32 + 2 * p;
            swt2[idx] = __floats2half2_rn(W[ch0 * 9 + tap], W[(ch0 + 1) * 9 + tap]);
        }
        if (tid < 32) sbv[tid] = (branch ? b1 : b0)[head * 32 + tid];
    }

    // ---- load Q,K rows + V (both layouts) ----
    {
        int w = tid;
        int l = (branch == 0) ? d * 1024 + (w >> 2) * 32 + g * 4 + (w & 3)
                              : d * 1024 + g * 128 + w;
        const uint4* src = (const uint4*)&qkv[(size_t)l * 1536 + cc];
        uint4 qv[4], kv[4], vv[4];
#pragma unroll
        for (int i = 0; i < 4; i++) { qv[i] = src[i]; kv[i] = src[64 + i]; vv[i] = src[128 + i]; }
#pragma unroll
        for (int i = 0; i < 4; i++) {
            *(uint4*)&qs[w * 40 + i * 8] = qv[i];
            *(uint4*)&ks[w * 40 + i * 8] = kv[i];
        }
        const __half* vh = (const __half*)vv;
#pragma unroll
        for (int c = 0; c < 32; c++) vt[c * 136 + w] = vh[c];
        const __half2* vh2 = (const __half2*)vv;
#pragma unroll
        for (int i = 0; i < 16; i++) *(__half2*)&vs2[w * 34 + 2 * i] = vh2[i];
    }
    __syncthreads();

    // ---- fused LePE: depthwise 3x3, channel pairs in half2 ----
    {
        int w = tid;
        int i, j;
        const int Hs = branch ? 4 : 32;
        const int Ws = branch ? 32 : 4;
        if (branch == 0) { i = w >> 2; j = w & 3; }
        else             { i = w >> 5; j = w & 31; }
        float accx[16], accy[16];
#pragma unroll
        for (int p = 0; p < 16; p++) { accx[p] = sbv[2 * p]; accy[p] = sbv[2 * p + 1]; }
        for (int di = -1; di <= 1; di++) {
            int ii = i + di;
            if (ii < 0 || ii >= Hs) continue;
            for (int dj = -1; dj <= 1; dj++) {
                int jj = j + dj;
                if (jj < 0 || jj >= Ws) continue;
                int wp = (branch == 0) ? (ii * 4 + jj) : (ii * 32 + jj);
                int tap = (di + 1) * 3 + (dj + 1);
#pragma unroll
                for (int p = 0; p < 16; p++) {
                    float2 v  = __half22float2(*(__half2*)&vs2[wp * 34 + 2 * p]);
                    float2 wt = __half22float2(swt2[tap * 16 + p]);
                    accx[p] += wt.x * v.x;
                    accy[p] += wt.y * v.y;
                }
            }
        }
#pragma unroll
        for (int p = 0; p < 16; p++)
            *(__half2*)&lp[w * 34 + 2 * p] = __floats2half2_rn(accx[p], accy[p]);
    }
    __syncthreads();

    const uint32_t qb = smem_u32(qs);
    const uint32_t kb = smem_u32(ks);
    const uint32_t vb = smem_u32(vt);

    uint32_t aq[2][2][4];
#pragma unroll
    for (int mt = 0; mt < 2; mt++)
#pragma unroll
        for (int kk = 0; kk < 2; kk++) {
            int row = warp * 32 + mt * 16 + (lane & 15);
            int col = kk * 16 + ((lane >> 4) << 3);
            ldm4(aq[mt][kk], qb + (uint32_t)(row * 40 + col) * 2);
        }

    float oacc[2][4][4];
#pragma unroll
    for (int i = 0; i < 2; i++)
#pragma unroll
        for (int j = 0; j < 4; j++)
#pragma unroll
            for (int k = 0; k < 4; k++) oacc[i][j][k] = 0.f;
    float lsum[2][2] = {{0.f, 0.f}, {0.f, 0.f}};
    // scale * log2(e): softmax via 2^t, t = s*scale*log2e
    const float c2 = 0.17677669529663687f * 1.4426950408889634f;

#pragma unroll 1
    for (int ch = 0; ch < 2; ch++) {
        float s[2][8][4];
#pragma unroll
        for (int i = 0; i < 2; i++)
#pragma unroll
            for (int j = 0; j < 8; j++)
#pragma unroll
                for (int k = 0; k < 4; k++) s[i][j][k] = 0.f;
#pragma unroll
        for (int kk = 0; kk < 2; kk++) {
            uint32_t kf[8][2];
#pragma unroll
            for (int pg = 0; pg < 4; pg++) {
                int row = ch * 64 + pg * 16 + ((lane >> 4) & 1) * 8 + (lane & 7);
                int col = kk * 16 + ((lane >> 3) & 1) * 8;
                uint32_t t4[4];
                ldm4(t4, kb + (uint32_t)(row * 40 + col) * 2);
                kf[pg * 2][0] = t4[0]; kf[pg * 2][1] = t4[1];
                kf[pg * 2 + 1][0] = t4[2]; kf[pg * 2 + 1][1] = t4[3];
            }
#pragma unroll
            for (int mt = 0; mt < 2; mt++)
#pragma unroll
                for (int nt = 0; nt < 8; nt++)
                    mma16816(s[mt][nt], aq[mt][kk], kf[nt]);
        }
        // ---- P = 2^(S*c2) via ex2.approx.f16x2; lsum in fp32 ----
        uint32_t pa[2][4][4];
#pragma unroll
        for (int mt = 0; mt < 2; mt++)
#pragma unroll
            for (int j = 0; j < 4; j++)
#pragma unroll
                for (int q2 = 0; q2 < 2; q2++) {
                    float t0 = fminf(s[mt][2 * j + q2][0] * c2, 15.f);
                    float t1 = fminf(s[mt][2 * j + q2][1] * c2, 15.f);
                    float t2 = fminf(s[mt][2 * j + q2][2] * c2, 15.f);
                    float t3 = fminf(s[mt][2 * j + q2][3] * c2, 15.f);
                    uint32_t p01 = packh2(t0, t1);
                    uint32_t p23 = packh2(t2, t3);
                    asm("ex2.approx.f16x2 %0, %1;" : "=r"(p01) : "r"(p01));
                    asm("ex2.approx.f16x2 %0, %1;" : "=r"(p23) : "r"(p23));
                    pa[mt][j][q2 * 2 + 0] = p01;
                    pa[mt][j][q2 * 2 + 1] = p23;
                    float2 f01 = __half22float2(*(__half2*)&p01);
                    float2 f23 = __half22float2(*(__half2*)&p23);
                    lsum[mt][0] += f01.x + f01.y;
                    lsum[mt][1] += f23.x + f23.y;
                }
#pragma unroll
        for (int j = 0; j < 4; j++) {
            uint32_t vf[4][2];
#pragma unroll
            for (int pg = 0; pg < 2; pg++) {
                int row = pg * 16 + ((lane >> 4) & 1) * 8 + (lane & 7);
                int col = ch * 64 + j * 16 + ((lane >> 3) & 1) * 8;
                uint32_t t4[4];
                ldm4(t4, vb + (uint32_t)(row * 136 + col) * 2);
                vf[pg * 2][0] = t4[0]; vf[pg * 2][1] = t4[1];
                vf[pg * 2 + 1][0] = t4[2]; vf[pg * 2 + 1][1] = t4[3];
            }
#pragma unroll
            for (int mt = 0; mt < 2; mt++)
#pragma unroll
                for (int nt = 0; nt < 4; nt++)
                    mma16816(oacc[mt][nt], pa[mt][j], vf[nt]);
        }
    }

#pragma unroll
    for (int mt = 0; mt < 2; mt++)
#pragma unroll
        for (int h = 0; h < 2; h++) {
            float v = lsum[mt][h];
            v += __shfl_xor_sync(0xffffffffu, v, 1);
            v += __shfl_xor_sync(0xffffffffu, v, 2);
            lsum[mt][h] = 1.f / v;
        }

#pragma unroll
    for (int mt = 0; mt < 2; mt++) {
        int w0r = warp * 32 + mt * 16 + (lane >> 2);
#pragma unroll
        for (int h = 0; h < 2; h++) {
            int w = w0r + h * 8;
            int l = (branch == 0) ? d * 1024 + (w >> 2) * 32 + g * 4 + (w & 3)
                                  : d * 1024 + g * 128 + w;
            __half* ap = att + (size_t)l * 512 + cc;
            float inv = lsum[mt][h];
#pragma unroll
            for (int nt = 0; nt < 4; nt++) {
                int col = nt * 8 + 2 * (lane & 3);
                float2 lep = __half22float2(*(__half2*)&lp[w * 34 + col]);
                *(__half2*)(ap + col) = __floats2half2_rn(
                    lep.x + oacc[mt][nt][h * 2 + 0] * inv,
                    lep.y + oacc[mt][nt][h * 2 + 1] * inv);
            }
        }
    }
}

// ======================= launch =======================
extern "C" void kernel_launch(void* const* d_in, const int* in_sizes, int n_in,
                              void* d_out, int out_size)
{
    const float* x    = (const float*)d_in[0];
    const float* n1g  = (const float*)d_in[1];
    const float* n1b  = (const float*)d_in[2];
    const float* qkvw = (const float*)d_in[3];
    const float* l0w  = (const float*)d_in[4];
    const float* l0b  = (const float*)d_in[5];
    const float* l1w  = (const float*)d_in[6];
    const float* l1b  = (const float*)d_in[7];
    const float* pw   = (const float*)d_in[8];
    const float* pb   = (const float*)d_in[9];
    const float* n2g  = (const float*)d_in[10];
    const float* n2b  = (const float*)d_in[11];
    const float* f1w  = (const float*)d_in[12];
    const float* f1b  = (const float*)d_in[13];
    const float* f2w  = (const float*)d_in[14];
    const float* f2b  = (const float*)d_in[15];
    float* out = (float*)d_out;

    __half *img, *wq, *wp, *w1, *w2, *qkv, *att, *h2, *mid;
    float *xf;
    cudaGetSymbolAddress((void**)&img, g_img);
    cudaGetSymbolAddress((void**)&wq,  g_wq);
    cudaGetSymbolAddress((void**)&wp,  g_wp);
    cudaGetSymbolAddress((void**)&w1,  g_w1);
    cudaGetSymbolAddress((void**)&w2,  g_w2);
    cudaGetSymbolAddress((void**)&qkv, g_qkvh);
    cudaGetSymbolAddress((void**)&att, g_att);
    cudaGetSymbolAddress((void**)&xf,  g_xf);
    cudaGetSymbolAddress((void**)&h2,  g_h2);
    cudaGetSymbolAddress((void**)&mid, g_mid);

    cudaFuncSetAttribute(gemm_hmma<1>, cudaFuncAttributeMaxDynamicSharedMemorySize, GEMM_SMEM_BYTES);
    cudaFuncSetAttribute(gemm_hmma<2>, cudaFuncAttributeMaxDynamicSharedMemorySize, GEMM_SMEM_BYTES);
    cudaFuncSetAttribute(gemm_hmma<3>, cudaFuncAttributeMaxDynamicSharedMemorySize, GEMM_SMEM_BYTES);
    cudaFuncSetAttribute(ln_kernel,    cudaFuncAttributeMaxDynamicSharedMemorySize, LN_SMEM_BYTES);

    // merged weight transposes (fp32 -> fp16, (K,N) -> (N,K))
    wtrans_all<<<3072, dim3(32, 8)>>>(qkvw, wq, pw, wp, f1w, w1, f2w, w2);

    // LN1
    ln_kernel<<<TOK / 32, 256, LN_SMEM_BYTES>>>(x, n1g, n1b, img);
    // QKV GEMM -> fp16 row-major
    gemm_hmma<3><<<dim3(12, 256), 256, GEMM_SMEM_BYTES>>>(img, wq, nullptr, nullptr, qkv, TOK, 1536, 512);
    // attention with fused LePE -> att (pure store)
    attn_hmma<<<4096, 128>>>(qkv, att, l0w, l0b, l1w, l1b);
    // proj + bias + x residual -> xf (C,L) fp32
    gemm_hmma<1><<<dim3(4, 256), 256, GEMM_SMEM_BYTES>>>(att, wp, pb, x, xf, TOK, 0, 512);
    // LN2
    ln_kernel<<<TOK / 32, 256, LN_SMEM_BYTES>>>(xf, n2g, n2b, h2);
    // fc1 + bias + gelu -> mid fp16 row-major
    gemm_hmma<2><<<dim3(16, 256), 256, GEMM_SMEM_BYTES>>>(h2, w1, f1b, nullptr, mid, TOK, 2048, 512);
    // fc2 + bias + xf residual -> out (C,L) fp32
    gemm_hmma<1><<<dim3(4, 256), 256, GEMM_SMEM_BYTES>>>(mid, w2, f2b, xf, out, TOK, 0, 2048);
}

// round 14
// speedup vs baseline: 5.4693x; 1.0134x over previous
#include <cuda_runtime.h>
#include <cuda_fp16.h>
#include <math.h>
#include <stdint.h>

#define TOK 32768

// ======================= scratch (no cudaMalloc allowed) =======================
__device__ __half g_img[(size_t)TOK * 512];     // LN1 out, (L,C) row-major fp16
__device__ __half g_wq [(size_t)1536 * 512];    // qkv_w^T  (N,K) fp16
__device__ __half g_wp [(size_t)512 * 512];     // proj_w^T
__device__ __half g_w1 [(size_t)2048 * 512];    // fc1_w^T
__device__ __half g_w2 [(size_t)512 * 2048];    // fc2_w^T
__device__ __half g_qkvh[(size_t)TOK * 1536];   // (L,3C) fp16 row-major
__device__ __half g_att[(size_t)TOK * 512];     // lepe+attn out, (L,C) fp16
__device__ float  g_xf [(size_t)512 * TOK];     // (C,L) fp32 col-major
__device__ __half g_h2 [(size_t)TOK * 512];     // LN2 out fp16 (L,C)
__device__ __half g_mid[(size_t)TOK * 2048];    // gelu(fc1) fp16 (L,2048)

// ======================= PTX helpers (sm_80-level only) =======================
__device__ __forceinline__ uint32_t smem_u32(const void* p) {
    uint32_t a;
    asm("{ .reg .u64 t; cvta.to.shared.u64 t, %1; cvt.u32.u64 %0, t; }" : "=r"(a) : "l"(p));
    return a;
}
__device__ __forceinline__ void ldm4(uint32_t* r, uint32_t a) {
    asm volatile("ldmatrix.sync.aligned.m8n8.x4.shared.b16 {%0,%1,%2,%3}, [%4];"
        : "=r"(r[0]), "=r"(r[1]), "=r"(r[2]), "=r"(r[3]) : "r"(a));
}
__device__ __forceinline__ void mma16816(float* d, const uint32_t* a, const uint32_t* b) {
    asm volatile("mma.sync.aligned.m16n8k16.row.col.f32.f16.f16.f32 "
        "{%0,%1,%2,%3}, {%4,%5,%6,%7}, {%8,%9}, {%0,%1,%2,%3};"
        : "+f"(d[0]), "+f"(d[1]), "+f"(d[2]), "+f"(d[3])
        : "r"(a[0]), "r"(a[1]), "r"(a[2]), "r"(a[3]), "r"(b[0]), "r"(b[1]));
}
__device__ __forceinline__ uint32_t packh2(float a, float b) {
    __half2 h = __floats2half2_rn(a, b);
    return *(uint32_t*)&h;
}
#define CP_ASYNC16(dst, src) \
    asm volatile("cp.async.cg.shared.global [%0], [%1], 16;" :: "r"(dst), "l"(src))
#define CP_COMMIT() asm volatile("cp.async.commit_group;" ::: "memory")
#define CP_WAIT1()  asm volatile("cp.async.wait_group 1;" ::: "memory")
#define CP_WAIT0()  asm volatile("cp.async.wait_group 0;" ::: "memory")

extern __shared__ char smem_raw[];

// ======================= HMMA GEMM (cp.async 2-stage, K-chunk 64) =======================
// C[M,N] = A[M,K](fp16 row-major) * Bw[N,K]^T (fp16, K contiguous per row)
// EPI 1: fp32 col-major out[n*M+m] = acc + bias[n] + res[n*M+m]
// EPI 2: fp16 row-major out = gelu(acc + bias[n]), ld=ldo
// EPI 3: fp16 row-major out = acc, ld=ldo
#define TSTR 72                 // smem row stride in halves (144 B)
#define GSTG (128 * TSTR)       // halves per stage per matrix
#define GEMM_SMEM_BYTES (4 * GSTG * 2)   // 2 stages x (A+B) = 73728 B

template<int EPI>
__global__ __launch_bounds__(256)
void gemm_hmma(const __half* __restrict__ A, const __half* __restrict__ Bw,
               const float* __restrict__ bias, const float* __restrict__ res,
               void* __restrict__ outp, int M, int ldo, int K)
{
    const int tid  = threadIdx.x;
    const int lane = tid & 31;
    const int warp = tid >> 5;
    const int wm = warp & 1;        // 2 warps along M
    const int wn = warp >> 1;       // 4 warps along N
    const int m0 = blockIdx.y * 128;
    const int n0 = blockIdx.x * 128;

    float acc[4][4][4];
#pragma unroll
    for (int i = 0; i < 4; i++)
#pragma unroll
        for (int j = 0; j < 4; j++)
#pragma unroll
            for (int k = 0; k < 4; k++) acc[i][j][k] = 0.f;

    const int chunks = K >> 6;           // K-chunk = 64
    const int grow = tid >> 3;           // 0..31 (4 groups of 32 rows)
    const int gcol = (tid & 7) * 8;      // halves: 8 lanes x 16B = full 128B row
    const uint32_t smb = smem_u32(smem_raw);

    auto issue = [&](int c) {
        int buf = c & 1;
        uint32_t sa = smb + (uint32_t)(buf * GSTG) * 2;
        uint32_t sb = smb + (uint32_t)((2 + buf) * GSTG) * 2;
#pragma unroll
        for (int i = 0; i < 4; i++) {
            int r = grow + i * 32;
            CP_ASYNC16(sa + (uint32_t)(r * TSTR + gcol) * 2,
                       &A [(size_t)(m0 + r) * K + c * 64 + gcol]);
            CP_ASYNC16(sb + (uint32_t)(r * TSTR + gcol) * 2,
                       &Bw[(size_t)(n0 + r) * K + c * 64 + gcol]);
        }
    };

    issue(0); CP_COMMIT();
    issue(1); CP_COMMIT();

    for (int c = 0; c < chunks; c++) {
        if (c + 1 < chunks) CP_WAIT1(); else CP_WAIT0();
        __syncthreads();

        const int buf = c & 1;
        const uint32_t baseA = smb + (uint32_t)(buf * GSTG) * 2;
        const uint32_t baseB = smb + (uint32_t)((2 + buf) * GSTG) * 2;
#pragma unroll
        for (int kk = 0; kk < 4; kk++) {
            uint32_t af[4][4];
#pragma unroll
            for (int mt = 0; mt < 4; mt++) {
                int row = wm * 64 + mt * 16 + (lane & 15);
                int col = kk * 16 + ((lane >> 4) << 3);
                ldm4(af[mt], baseA + (uint32_t)(row * TSTR + col) * 2);
            }
            uint32_t bf[4][2];
#pragma unroll
            for (int pr = 0; pr < 2; pr++) {
                int row = wn * 32 + pr * 16 + ((lane >> 4) & 1) * 8 + (lane & 7);
                int col = kk * 16 + ((lane >> 3) & 1) * 8;
                uint32_t t4[4];
                ldm4(t4, baseB + (uint32_t)(row * TSTR + col) * 2);
                bf[pr * 2][0] = t4[0]; bf[pr * 2][1] = t4[1];
                bf[pr * 2 + 1][0] = t4[2]; bf[pr * 2 + 1][1] = t4[3];
            }
#pragma unroll
            for (int mt = 0; mt < 4; mt++)
#pragma unroll
                for (int nt = 0; nt < 4; nt++)
                    mma16816(acc[mt][nt], af[mt], bf[nt]);
        }
        if (c + 2 < chunks) {
            __syncthreads();          // all reads of buf done before overwrite
            issue(c + 2); CP_COMMIT();
        }
    }

    // ---------------- epilogue ----------------
#pragma unroll
    for (int mt = 0; mt < 4; mt++) {
        int r = m0 + wm * 64 + mt * 16 + (lane >> 2);
#pragma unroll
        for (int nt = 0; nt < 4; nt++) {
            int cN = n0 + wn * 32 + nt * 8 + 2 * (lane & 3);
            float v0 = acc[mt][nt][0], v1 = acc[mt][nt][1];
            float v2 = acc[mt][nt][2], v3 = acc[mt][nt][3];
            if (EPI == 1 || EPI == 2) {
                float b0 = __ldg(&bias[cN]), b1 = __ldg(&bias[cN + 1]);
                v0 += b0; v1 += b1; v2 += b0; v3 += b1;
            }
            if (EPI == 2) {
                v0 = 0.5f * v0 * (1.f + erff(v0 * 0.70710678118654752f));
                v1 = 0.5f * v1 * (1.f + erff(v1 * 0.70710678118654752f));
                v2 = 0.5f * v2 * (1.f + erff(v2 * 0.70710678118654752f));
                v3 = 0.5f * v3 * (1.f + erff(v3 * 0.70710678118654752f));
            }
            if (EPI == 1) {
                float* o = (float*)outp;
                size_t i00 = (size_t)cN * M + r;
                size_t i01 = (size_t)(cN + 1) * M + r;
                v0 += __ldg(&res[i00]);     v1 += __ldg(&res[i01]);
                v2 += __ldg(&res[i00 + 8]); v3 += __ldg(&res[i01 + 8]);
                o[i00] = v0; o[i01] = v1; o[i00 + 8] = v2; o[i01 + 8] = v3;
            } else {
                __half* o = (__half*)outp;
                *(__half2*)&o[(size_t)r * ldo + cN]       = __floats2half2_rn(v0, v1);
                *(__half2*)&o[(size_t)(r + 8) * ldo + cN] = __floats2half2_rn(v2, v3);
            }
        }
    }
}

// ======================= merged weight transpose + fp16 convert =======================
__global__ void wtrans_all(const float* __restrict__ qkvw, __half* __restrict__ wq,
                           const float* __restrict__ pw,   __half* __restrict__ wp,
                           const float* __restrict__ f1w,  __half* __restrict__ w1,
                           const float* __restrict__ f2w,  __half* __restrict__ w2)
{
    __shared__ float s[32][33];
    int b = blockIdx.x;
    const float* w; __half* wT; int K, N, t;
    if (b < 768)       { w = qkvw; wT = wq; K = 512;  N = 1536; t = b; }
    else if (b < 1024) { w = pw;   wT = wp; K = 512;  N = 512;  t = b - 768; }
    else if (b < 2048) { w = f1w;  wT = w1; K = 512;  N = 2048; t = b - 1024; }
    else               { w = f2w;  wT = w2; K = 2048; N = 512;  t = b - 2048; }
    int tx0 = N >> 5;
    int n0 = (t % tx0) * 32, k0 = (t / tx0) * 32;
    int tx = threadIdx.x, ty = threadIdx.y;
    for (int i = ty; i < 32; i += 8) s[i][tx] = w[(size_t)(k0 + i) * N + n0 + tx];
    __syncthreads();
    for (int i = ty; i < 32; i += 8) wT[(size_t)(n0 + i) * K + k0 + tx] = __float2half(s[tx][i]);
}

// ======================= LN: (C,L) fp32 -> (L,C) fp16, single gmem pass =======================
#define LNSTR 517
#define LN_SMEM_BYTES (32 * LNSTR * 4)
__global__ __launch_bounds__(256)
void ln_kernel(const float* __restrict__ in, const float* __restrict__ g,
               const float* __restrict__ b, __half* __restrict__ out)
{
    float* stg = (float*)smem_raw;     // [32][LNSTR]
    __shared__ float red[512];
    __shared__ float ms[32], rs[32];
    int tx = threadIdx.x & 31, ty = threadIdx.x >> 5;
    int tok = blockIdx.x * 32 + tx;
    float sum = 0.f, sq = 0.f;
    for (int c = ty; c < 512; c += 8) {
        float x = in[(size_t)c * TOK + tok];
        stg[tx * LNSTR + c] = x;
        sum += x; sq += x * x;
    }
    red[ty * 32 + tx] = sum; red[256 + ty * 32 + tx] = sq;
    __syncthreads();
    if (ty == 0) {
        float s = 0.f, q = 0.f;
        for (int j = 0; j < 8; j++) { s += red[j * 32 + tx]; q += red[256 + j * 32 + tx]; }
        float mean = s * (1.f / 512.f);
        float var  = q * (1.f / 512.f) - mean * mean;
        ms[tx] = mean; rs[tx] = rsqrtf(var + 1e-5f);
    }
    __syncthreads();
    size_t base = (size_t)blockIdx.x * 32 * 512;
#pragma unroll
    for (int i = 0; i < 8; i++) {
        int id = threadIdx.x + i * 256;
        int row = id >> 6, c8 = (id & 63) * 8;
        float mean = ms[row], rstd = rs[row];
        __half h[8];
#pragma unroll
        for (int j = 0; j < 8; j++) {
            int c = c8 + j;
            h[j] = __float2half((stg[row * LNSTR + c] - mean) * rstd * g[c] + b[c]);
        }
        *(uint4*)&out[base + (size_t)row * 512 + c8] = *(uint4*)h;
    }
}

// ======================= HMMA windowed attention + fused LePE =======================
// exp via ex2.approx.f16x2; half2 lepe; vs2 smem reused as lepe buffer (occupancy).
__global__ __launch_bounds__(128, 5)
void attn_hmma(const __half* __restrict__ qkv, __half* __restrict__ att,
               const float* __restrict__ w0, const float* __restrict__ b0,
               const float* __restrict__ w1, const float* __restrict__ b1)
{
    __shared__ __half qs[128 * 40];
    __shared__ __half ks[128 * 40];
    __shared__ __half vt[32 * 136];    // V transposed: [channel][token] (for PV mma)
    __shared__ __half vs2[128 * 34];   // V token-major (lepe input), then lepe output
    __shared__ __half2 swt2[144];      // conv weights [tap][chpair]
    __shared__ float sbv[32];
    const int tid = threadIdx.x;
    const int lane = tid & 31, warp = tid >> 5;
    const int bid = blockIdx.x;
    const int head = bid & 7;
    const int widx = (bid >> 3) & 255;
    const int branch = bid >> 11;
    const int d = widx >> 3, g = widx & 7;
    const int cc = branch * 256 + head * 32;

    // ---- conv weights: half2 per channel pair, [tap][pair] ----
    {
        const float* W  = branch ? w1 : w0;
        for (int idx = tid; idx < 144; idx += 128) {
            int tap = idx >> 4, p = idx & 15;
            int ch0 = head * 32 + 2 * p;
            swt2[idx] = __floats2half2_rn(W[ch0 * 9 + tap], W[(ch0 + 1) * 9 + tap]);
        }
        if (tid < 32) sbv[tid] = (branch ? b1 : b0)[head * 32 + tid];
    }

    // ---- load Q,K rows + V (both layouts) ----
    {
        int w = tid;
        int l = (branch == 0) ? d * 1024 + (w >> 2) * 32 + g * 4 + (w & 3)
                              : d * 1024 + g * 128 + w;
        const uint4* src = (const uint4*)&qkv[(size_t)l * 1536 + cc];
        uint4 qv[4], kv[4], vv[4];
#pragma unroll
        for (int i = 0; i < 4; i++) { qv[i] = src[i]; kv[i] = src[64 + i]; vv[i] = src[128 + i]; }
#pragma unroll
        for (int i = 0; i < 4; i++) {
            *(uint4*)&qs[w * 40 + i * 8] = qv[i];
            *(uint4*)&ks[w * 40 + i * 8] = kv[i];
        }
        const __half* vh = (const __half*)vv;
#pragma unroll
        for (int c = 0; c < 32; c++) vt[c * 136 + w] = vh[c];
        const __half2* vh2 = (const __half2*)vv;
#pragma unroll
        for (int i = 0; i < 16; i++) *(__half2*)&vs2[w * 34 + 2 * i] = vh2[i];
    }
    __syncthreads();

    // ---- fused LePE into registers (reads vs2) ----
    float accx[16], accy[16];
    {
        int w = tid;
        int i, j;
        const int Hs = branch ? 4 : 32;
        const int Ws = branch ? 32 : 4;
        if (branch == 0) { i = w >> 2; j = w & 3; }
        else             { i = w >> 5; j = w & 31; }
#pragma unroll
        for (int p = 0; p < 16; p++) { accx[p] = sbv[2 * p]; accy[p] = sbv[2 * p + 1]; }
        for (int di = -1; di <= 1; di++) {
            int ii = i + di;
            if (ii < 0 || ii >= Hs) continue;
            for (int dj = -1; dj <= 1; dj++) {
                int jj = j + dj;
                if (jj < 0 || jj >= Ws) continue;
                int wp = (branch == 0) ? (ii * 4 + jj) : (ii * 32 + jj);
                int tap = (di + 1) * 3 + (dj + 1);
#pragma unroll
                for (int p = 0; p < 16; p++) {
                    float2 v  = __half22float2(*(__half2*)&vs2[wp * 34 + 2 * p]);
                    float2 wt = __half22float2(swt2[tap * 16 + p]);
                    accx[p] += wt.x * v.x;
                    accy[p] += wt.y * v.y;
                }
            }
        }
    }
    __syncthreads();                    // all lepe reads of vs2 complete
    // ---- store lepe into vs2 (now "lp") ----
    {
        int w = tid;
#pragma unroll
        for (int p = 0; p < 16; p++)
            *(__half2*)&vs2[w * 34 + 2 * p] = __floats2half2_rn(accx[p], accy[p]);
    }

    const uint32_t qb = smem_u32(qs);
    const uint32_t kb = smem_u32(ks);
    const uint32_t vb = smem_u32(vt);

    uint32_t aq[2][2][4];
#pragma unroll
    for (int mt = 0; mt < 2; mt++)
#pragma unroll
        for (int kk = 0; kk < 2; kk++) {
            int row = warp * 32 + mt * 16 + (lane & 15);
            int col = kk * 16 + ((lane >> 4) << 3);
            ldm4(aq[mt][kk], qb + (uint32_t)(row * 40 + col) * 2);
        }
    __syncthreads();                    // lp stores visible to all

    float oacc[2][4][4];
#pragma unroll
    for (int i = 0; i < 2; i++)
#pragma unroll
        for (int j = 0; j < 4; j++)
#pragma unroll
            for (int k = 0; k < 4; k++) oacc[i][j][k] = 0.f;
    float lsum[2][2] = {{0.f, 0.f}, {0.f, 0.f}};
    const float c2 = 0.17677669529663687f * 1.4426950408889634f;

#pragma unroll 1
    for (int ch = 0; ch < 2; ch++) {
        float s[2][8][4];
#pragma unroll
        for (int i = 0; i < 2; i++)
#pragma unroll
            for (int j = 0; j < 8; j++)
#pragma unroll
                for (int k = 0; k < 4; k++) s[i][j][k] = 0.f;
#pragma unroll
        for (int kk = 0; kk < 2; kk++) {
            uint32_t kf[8][2];
#pragma unroll
            for (int pg = 0; pg < 4; pg++) {
                int row = ch * 64 + pg * 16 + ((lane >> 4) & 1) * 8 + (lane & 7);
                int col = kk * 16 + ((lane >> 3) & 1) * 8;
                uint32_t t4[4];
                ldm4(t4, kb + (uint32_t)(row * 40 + col) * 2);
                kf[pg * 2][0] = t4[0]; kf[pg * 2][1] = t4[1];
                kf[pg * 2 + 1][0] = t4[2]; kf[pg * 2 + 1][1] = t4[3];
            }
#pragma unroll
            for (int mt = 0; mt < 2; mt++)
#pragma unroll
                for (int nt = 0; nt < 8; nt++)
                    mma16816(s[mt][nt], aq[mt][kk], kf[nt]);
        }
        uint32_t pa[2][4][4];
#pragma unroll
        for (int mt = 0; mt < 2; mt++)
#pragma unroll
            for (int j = 0; j < 4; j++)
#pragma unroll
                for (int q2 = 0; q2 < 2; q2++) {
                    float t0 = fminf(s[mt][2 * j + q2][0] * c2, 15.f);
                    float t1 = fminf(s[mt][2 * j + q2][1] * c2, 15.f);
                    float t2 = fminf(s[mt][2 * j + q2][2] * c2, 15.f);
                    float t3 = fminf(s[mt][2 * j + q2][3] * c2, 15.f);
                    uint32_t p01 = packh2(t0, t1);
                    uint32_t p23 = packh2(t2, t3);
                    asm("ex2.approx.f16x2 %0, %1;" : "=r"(p01) : "r"(p01));
                    asm("ex2.approx.f16x2 %0, %1;" : "=r"(p23) : "r"(p23));
                    pa[mt][j][q2 * 2 + 0] = p01;
                    pa[mt][j][q2 * 2 + 1] = p23;
                    float2 f01 = __half22float2(*(__half2*)&p01);
                    float2 f23 = __half22float2(*(__half2*)&p23);
                    lsum[mt][0] += f01.x + f01.y;
                    lsum[mt][1] += f23.x + f23.y;
                }
#pragma unroll
        for (int j = 0; j < 4; j++) {
            uint32_t vf[4][2];
#pragma unroll
            for (int pg = 0; pg < 2; pg++) {
                int row = pg * 16 + ((lane >> 4) & 1) * 8 + (lane & 7);
                int col = ch * 64 + j * 16 + ((lane >> 3) & 1) * 8;
                uint32_t t4[4];
                ldm4(t4, vb + (uint32_t)(row * 136 + col) * 2);
                vf[pg * 2][0] = t4[0]; vf[pg * 2][1] = t4[1];
                vf[pg * 2 + 1][0] = t4[2]; vf[pg * 2 + 1][1] = t4[3];
            }
#pragma unroll
            for (int mt = 0; mt < 2; mt++)
#pragma unroll
                for (int nt = 0; nt < 4; nt++)
                    mma16816(oacc[mt][nt], pa[mt][j], vf[nt]);
        }
    }

#pragma unroll
    for (int mt = 0; mt < 2; mt++)
#pragma unroll
        for (int h = 0; h < 2; h++) {
            float v = lsum[mt][h];
            v += __shfl_xor_sync(0xffffffffu, v, 1);
            v += __shfl_xor_sync(0xffffffffu, v, 2);
            lsum[mt][h] = 1.f / v;
        }

#pragma unroll
    for (int mt = 0; mt < 2; mt++) {
        int w0r = warp * 32 + mt * 16 + (lane >> 2);
#pragma unroll
        for (int h = 0; h < 2; h++) {
            int w = w0r + h * 8;
            int l = (branch == 0) ? d * 1024 + (w >> 2) * 32 + g * 4 + (w & 3)
                                  : d * 1024 + g * 128 + w;
            __half* ap = att + (size_t)l * 512 + cc;
            float inv = lsum[mt][h];
#pragma unroll
            for (int nt = 0; nt < 4; nt++) {
                int col = nt * 8 + 2 * (lane & 3);
                float2 lep = __half22float2(*(__half2*)&vs2[w * 34 + col]);
                *(__half2*)(ap + col) = __floats2half2_rn(
                    lep.x + oacc[mt][nt][h * 2 + 0] * inv,
                    lep.y + oacc[mt][nt][h * 2 + 1] * inv);
            }
        }
    }
}

// ======================= launch =======================
extern "C" void kernel_launch(void* const* d_in, const int* in_sizes, int n_in,
                              void* d_out, int out_size)
{
    const float* x    = (const float*)d_in[0];
    const float* n1g  = (const float*)d_in[1];
    const float* n1b  = (const float*)d_in[2];
    const float* qkvw = (const float*)d_in[3];
    const float* l0w  = (const float*)d_in[4];
    const float* l0b  = (const float*)d_in[5];
    const float* l1w  = (const float*)d_in[6];
    const float* l1b  = (const float*)d_in[7];
    const float* pw   = (const float*)d_in[8];
    const float* pb   = (const float*)d_in[9];
    const float* n2g  = (const float*)d_in[10];
    const float* n2b  = (const float*)d_in[11];
    const float* f1w  = (const float*)d_in[12];
    const float* f1b  = (const float*)d_in[13];
    const float* f2w  = (const float*)d_in[14];
    const float* f2b  = (const float*)d_in[15];
    float* out = (float*)d_out;

    __half *img, *wq, *wp, *w1, *w2, *qkv, *att, *h2, *mid;
    float *xf;
    cudaGetSymbolAddress((void**)&img, g_img);
    cudaGetSymbolAddress((void**)&wq,  g_wq);
    cudaGetSymbolAddress((void**)&wp,  g_wp);
    cudaGetSymbolAddress((void**)&w1,  g_w1);
    cudaGetSymbolAddress((void**)&w2,  g_w2);
    cudaGetSymbolAddress((void**)&qkv, g_qkvh);
    cudaGetSymbolAddress((void**)&att, g_att);
    cudaGetSymbolAddress((void**)&xf,  g_xf);
    cudaGetSymbolAddress((void**)&h2,  g_h2);
    cudaGetSymbolAddress((void**)&mid, g_mid);

    cudaFuncSetAttribute(gemm_hmma<1>, cudaFuncAttributeMaxDynamicSharedMemorySize, GEMM_SMEM_BYTES);
    cudaFuncSetAttribute(gemm_hmma<2>, cudaFuncAttributeMaxDynamicSharedMemorySize, GEMM_SMEM_BYTES);
    cudaFuncSetAttribute(gemm_hmma<3>, cudaFuncAttributeMaxDynamicSharedMemorySize, GEMM_SMEM_BYTES);
    cudaFuncSetAttribute(ln_kernel,    cudaFuncAttributeMaxDynamicSharedMemorySize, LN_SMEM_BYTES);

    // merged weight transposes (fp32 -> fp16, (K,N) -> (N,K))
    wtrans_all<<<3072, dim3(32, 8)>>>(qkvw, wq, pw, wp, f1w, w1, f2w, w2);

    // LN1
    ln_kernel<<<TOK / 32, 256, LN_SMEM_BYTES>>>(x, n1g, n1b, img);
    // QKV GEMM -> fp16 row-major
    gemm_hmma<3><<<dim3(12, 256), 256, GEMM_SMEM_BYTES>>>(img, wq, nullptr, nullptr, qkv, TOK, 1536, 512);
    // attention with fused LePE -> att (pure store)
    attn_hmma<<<4096, 128>>>(qkv, att, l0w, l0b, l1w, l1b);
    // proj + bias + x residual -> xf (C,L) fp32
    gemm_hmma<1><<<dim3(4, 256), 256, GEMM_SMEM_BYTES>>>(att, wp, pb, x, xf, TOK, 0, 512);
    // LN2
    ln_kernel<<<TOK / 32, 256, LN_SMEM_BYTES>>>(xf, n2g, n2b, h2);
    // fc1 + bias + gelu -> mid fp16 row-major
    gemm_hmma<2><<<dim3(16, 256), 256, GEMM_SMEM_BYTES>>>(h2, w1, f1b, nullptr, mid, TOK, 2048, 512);
    // fc2 + bias + xf residual -> out (C,L) fp32
    gemm_hmma<1><<<dim3(4, 256), 256, GEMM_SMEM_BYTES>>>(mid, w2, f2b, xf, out, TOK, 0, 2048);
}